// round 1
// baseline (speedup 1.0000x reference)
#include <cuda_runtime.h>
#include <math.h>

// Problem constants
constexpr int Bn = 4, Sn = 1024, Tn = 1024, Dn = 1024, Fn = 4096, Hn = 16, HDn = 64;
constexpr int Mrows = Bn * Sn;           // 4096
constexpr float SCALE = 0.125f;          // 1/sqrt(64)

// ---------------- scratch (static device globals: allocation-free) -------------
__device__ float g_ln  [Mrows * Dn];            // 16 MB  LN output
__device__ float g_qkv [Mrows * 3 * Dn];        // 48 MB  qkv projection
__device__ float g_q   [Mrows * Dn];            // 16 MB  cross-attn q
__device__ float g_kv  [Mrows * 2 * Dn];        // 32 MB  cross-attn kv
__device__ float g_ctx [Mrows * Dn];            // 16 MB  attention context
__device__ float g_h   [Mrows * Dn];            // 16 MB  hidden (h2/h3)
__device__ float g_ffn [(size_t)Mrows * Fn];    // 64 MB  ffn intermediate
__device__ float g_sc  [(size_t)Bn * Hn * Sn * Tn]; // 256 MB attention scores

// ---------------- 4x4 micro-kernel macro ---------------------------------------
#define MICRO_FMA(a, b)                                                              \
    acc[0][0] += a.x * b.x; acc[0][1] += a.x * b.y; acc[0][2] += a.x * b.z; acc[0][3] += a.x * b.w; \
    acc[1][0] += a.y * b.x; acc[1][1] += a.y * b.y; acc[1][2] += a.y * b.z; acc[1][3] += a.y * b.w; \
    acc[2][0] += a.z * b.x; acc[2][1] += a.z * b.y; acc[2][2] += a.z * b.z; acc[2][3] += a.z * b.w; \
    acc[3][0] += a.w * b.x; acc[3][1] += a.w * b.y; acc[3][2] += a.w * b.z; acc[3][3] += a.w * b.w;

// ---------------- generic GEMM: C = act(A@W + bias) [+ residual] ----------------
// A: [M,K] row-major, W: [K,N] row-major, C/res: [M,N]. 64x64 tile, BK=16.
__global__ __launch_bounds__(256) void gemm64(
    const float* __restrict__ A, const float* __restrict__ W,
    const float* __restrict__ bias, const float* __restrict__ res,
    float* __restrict__ C, int M, int N, int K, int gelu)
{
    __shared__ __align__(16) float As[16][68];
    __shared__ __align__(16) float Ws[16][68];
    const int tid  = threadIdx.x;
    const int tx   = tid & 15, ty = tid >> 4;
    const int col0 = blockIdx.x * 64, row0 = blockIdx.y * 64;

    const int ka = tid & 15, ma = tid >> 4;   // A-tile load indices
    const int nw = tid & 63, kw = tid >> 6;   // W-tile load indices
    const float* Ap = A + (size_t)row0 * K;
    const float* Wp = W + col0;

    float acc[4][4] = {};
    for (int kt = 0; kt < K; kt += 16) {
        #pragma unroll
        for (int i = 0; i < 4; i++)
            As[ka][ma + i * 16] = Ap[(size_t)(ma + i * 16) * K + kt + ka];
        #pragma unroll
        for (int i = 0; i < 4; i++)
            Ws[kw + i * 4][nw] = Wp[(size_t)(kt + kw + i * 4) * N + nw];
        __syncthreads();
        #pragma unroll
        for (int kk = 0; kk < 16; kk++) {
            float4 a = *(const float4*)&As[kk][ty * 4];
            float4 b = *(const float4*)&Ws[kk][tx * 4];
            MICRO_FMA(a, b)
        }
        __syncthreads();
    }

    #pragma unroll
    for (int i = 0; i < 4; i++) {
        int m = row0 + ty * 4 + i;
        #pragma unroll
        for (int j = 0; j < 4; j++) {
            int n = col0 + tx * 4 + j;
            float v = acc[i][j] + bias[n];
            if (gelu) v = 0.5f * v * (1.0f + erff(v * 0.7071067811865476f));
            if (res)  v += res[(size_t)m * N + n];
            C[(size_t)m * N + n] = v;
        }
    }
}

// ---------------- batched attention scores: sc[z,s,t] = Q(z,s,:).K(z,t,:) -------
// z = b*16+h. Q row ptr: qbase + (b*S+s)*ldq + h*64 ; K: kbase + (b*T+t)*ldk + koff + h*64
__global__ __launch_bounds__(256) void attn_scores(
    const float* __restrict__ qbase, int ldq,
    const float* __restrict__ kbase, int ldk, int koff,
    float* __restrict__ sc)
{
    __shared__ __align__(16) float Qs[64][68];
    __shared__ __align__(16) float Ks[64][68];
    const int z = blockIdx.z, b = z >> 4, h = z & 15;
    const int t0 = blockIdx.x * 64, s0 = blockIdx.y * 64;
    const float* Qp = qbase + (size_t)b * Sn * ldq + h * 64;
    const float* Kp = kbase + (size_t)b * Tn * ldk + koff + h * 64;

    const int tid = threadIdx.x;
    const int d = tid & 63, r = tid >> 6;
    #pragma unroll
    for (int i = 0; i < 16; i++) {
        Qs[d][r + i * 4] = Qp[(size_t)(s0 + r + i * 4) * ldq + d];
        Ks[d][r + i * 4] = Kp[(size_t)(t0 + r + i * 4) * ldk + d];
    }
    __syncthreads();

    const int tx = tid & 15, ty = tid >> 4;
    float acc[4][4] = {};
    #pragma unroll 16
    for (int kk = 0; kk < 64; kk++) {
        float4 a = *(const float4*)&Qs[kk][ty * 4];
        float4 b4 = *(const float4*)&Ks[kk][tx * 4];
        MICRO_FMA(a, b4)
    }

    float* out = sc + ((size_t)z * Sn + s0) * Tn + t0;
    #pragma unroll
    for (int i = 0; i < 4; i++)
        #pragma unroll
        for (int j = 0; j < 4; j++)
            out[(size_t)(ty * 4 + i) * Tn + tx * 4 + j] = acc[i][j];
}

// ---------------- row softmax with mask semantics of the reference --------------
// causal: v = raw*scale for t<=s, else -10000 exactly. cross: v = raw*scale + mask[b,t]
__global__ __launch_bounds__(256) void softmax_rows(
    float* __restrict__ sc, float scale, int causal, const float* __restrict__ addmask)
{
    const int row = blockIdx.x;               // z*S + s, z = b*16+h
    const int s = row & (Sn - 1);
    const int b = row >> 14;                  // / (S*H) = / 16384
    float* p = sc + (size_t)row * Tn;
    const int tid = threadIdx.x;

    float vals[4];
    float mx = -1e30f;
    #pragma unroll
    for (int i = 0; i < 4; i++) {
        int c = tid + i * 256;
        float v = p[c] * scale;
        if (causal) { if (c > s) v = -10000.0f; }
        else if (addmask) v += addmask[(size_t)b * Tn + c];
        vals[i] = v;
        mx = fmaxf(mx, v);
    }
    __shared__ float sm[18];
    // max reduce
    #pragma unroll
    for (int off = 16; off > 0; off >>= 1) mx = fmaxf(mx, __shfl_xor_sync(~0u, mx, off));
    if ((tid & 31) == 0) sm[tid >> 5] = mx;
    __syncthreads();
    if (tid < 32) {
        float a = (tid < 8) ? sm[tid] : -1e30f;
        #pragma unroll
        for (int off = 4; off > 0; off >>= 1) a = fmaxf(a, __shfl_xor_sync(~0u, a, off));
        if (tid == 0) sm[16] = a;
    }
    __syncthreads();
    const float m = sm[16];

    float sum = 0.f;
    #pragma unroll
    for (int i = 0; i < 4; i++) { vals[i] = expf(vals[i] - m); sum += vals[i]; }
    #pragma unroll
    for (int off = 16; off > 0; off >>= 1) sum += __shfl_xor_sync(~0u, sum, off);
    if ((tid & 31) == 0) sm[tid >> 5] = sum;
    __syncthreads();
    if (tid < 32) {
        float a = (tid < 8) ? sm[tid] : 0.f;
        #pragma unroll
        for (int off = 4; off > 0; off >>= 1) a += __shfl_xor_sync(~0u, a, off);
        if (tid == 0) sm[17] = a;
    }
    __syncthreads();
    const float inv = 1.0f / sm[17];
    #pragma unroll
    for (int i = 0; i < 4; i++) p[tid + i * 256] = vals[i] * inv;
}

// ---------------- batched context: ctx[b,s,h*64+d] = sum_t P[z,s,t] V(z,t,d) ----
__global__ __launch_bounds__(256) void attn_ctx(
    const float* __restrict__ sc,
    const float* __restrict__ vbase, int ldv, int voff,
    float* __restrict__ ctx)
{
    __shared__ __align__(16) float Ps[16][68];
    __shared__ __align__(16) float Vs[16][68];
    const int z = blockIdx.z, b = z >> 4, h = z & 15;
    const int s0 = blockIdx.y * 64;
    const float* Pp = sc + ((size_t)z * Sn + s0) * Tn;
    const float* Vp = vbase + (size_t)b * Tn * ldv + voff + h * 64;

    const int tid = threadIdx.x;
    const int kp = tid & 15, rp = tid >> 4;
    const int nv = tid & 63, kv = tid >> 6;
    const int tx = tid & 15, ty = tid >> 4;

    float acc[4][4] = {};
    for (int kt = 0; kt < Tn; kt += 16) {
        #pragma unroll
        for (int i = 0; i < 4; i++)
            Ps[kp][rp + i * 16] = Pp[(size_t)(rp + i * 16) * Tn + kt + kp];
        #pragma unroll
        for (int i = 0; i < 4; i++)
            Vs[kv + i * 4][nv] = Vp[(size_t)(kt + kv + i * 4) * ldv + nv];
        __syncthreads();
        #pragma unroll
        for (int kk = 0; kk < 16; kk++) {
            float4 a = *(const float4*)&Ps[kk][ty * 4];
            float4 b4 = *(const float4*)&Vs[kk][tx * 4];
            MICRO_FMA(a, b4)
        }
        __syncthreads();
    }

    float* out = ctx + (size_t)(b * Sn + s0) * Dn + h * 64;
    #pragma unroll
    for (int i = 0; i < 4; i++)
        #pragma unroll
        for (int j = 0; j < 4; j++)
            out[(size_t)(ty * 4 + i) * Dn + tx * 4 + j] = acc[i][j];
}

// ---------------- LayerNorm: one block per row, D=1024 = 256 threads x float4 ---
__global__ __launch_bounds__(256) void layernorm_rows(
    const float* __restrict__ x, const float* __restrict__ w,
    const float* __restrict__ bb, float* __restrict__ y)
{
    const int row = blockIdx.x, tid = threadIdx.x;
    float4 v = ((const float4*)(x + (size_t)row * Dn))[tid];
    float s  = v.x + v.y + v.z + v.w;
    float sq = v.x * v.x + v.y * v.y + v.z * v.z + v.w * v.w;

    __shared__ float sm[18];
    #pragma unroll
    for (int off = 16; off > 0; off >>= 1) {
        s  += __shfl_xor_sync(~0u, s,  off);
        sq += __shfl_xor_sync(~0u, sq, off);
    }
    if ((tid & 31) == 0) { sm[tid >> 5] = s; sm[(tid >> 5) + 8] = sq; }
    __syncthreads();
    if (tid < 32) {
        float a  = (tid < 8) ? sm[tid]     : 0.f;
        float aq = (tid < 8) ? sm[tid + 8] : 0.f;
        #pragma unroll
        for (int off = 4; off > 0; off >>= 1) {
            a  += __shfl_xor_sync(~0u, a,  off);
            aq += __shfl_xor_sync(~0u, aq, off);
        }
        if (tid == 0) { sm[16] = a; sm[17] = aq; }
    }
    __syncthreads();
    const float mean = sm[16] * (1.0f / Dn);
    const float var  = sm[17] * (1.0f / Dn) - mean * mean;
    const float rstd = rsqrtf(var + 1e-12f);

    float4 w4 = ((const float4*)w)[tid];
    float4 b4 = ((const float4*)bb)[tid];
    float4 o;
    o.x = w4.x * (v.x - mean) * rstd + b4.x;
    o.y = w4.y * (v.y - mean) * rstd + b4.y;
    o.z = w4.z * (v.z - mean) * rstd + b4.z;
    o.w = w4.w * (v.w - mean) * rstd + b4.w;
    ((float4*)(y + (size_t)row * Dn))[tid] = o;
}

// -------------------------------- launcher --------------------------------------
extern "C" void kernel_launch(void* const* d_in, const int* in_sizes, int n_in,
                              void* d_out, int out_size)
{
    const float* hid      = (const float*)d_in[0];
    const float* enc      = (const float*)d_in[1];
    const float* enc_mask = (const float*)d_in[2];
    // d_in[3] dec_attn_mask: tril, reproduced via index comparison in softmax
    const float *ln1_w = (const float*)d_in[4],  *ln1_b = (const float*)d_in[5];
    const float *qkv_w = (const float*)d_in[6],  *qkv_b = (const float*)d_in[7];
    const float *ao_w  = (const float*)d_in[8],  *ao_b  = (const float*)d_in[9];
    const float *ln2_w = (const float*)d_in[10], *ln2_b = (const float*)d_in[11];
    const float *q_w   = (const float*)d_in[12], *q_b   = (const float*)d_in[13];
    const float *kv_w  = (const float*)d_in[14], *kv_b  = (const float*)d_in[15];
    const float *co_w  = (const float*)d_in[16], *co_b  = (const float*)d_in[17];
    const float *ln3_w = (const float*)d_in[18], *ln3_b = (const float*)d_in[19];
    const float *fi_w  = (const float*)d_in[20], *fi_b  = (const float*)d_in[21];
    const float *fo_w  = (const float*)d_in[22], *fo_b  = (const float*)d_in[23];
    float* out = (float*)d_out;

    float *ln, *qkv, *qb, *kvb, *ctx, *hb, *ffn, *sc;
    cudaGetSymbolAddress((void**)&ln,  g_ln);
    cudaGetSymbolAddress((void**)&qkv, g_qkv);
    cudaGetSymbolAddress((void**)&qb,  g_q);
    cudaGetSymbolAddress((void**)&kvb, g_kv);
    cudaGetSymbolAddress((void**)&ctx, g_ctx);
    cudaGetSymbolAddress((void**)&hb,  g_h);
    cudaGetSymbolAddress((void**)&ffn, g_ffn);
    cudaGetSymbolAddress((void**)&sc,  g_sc);

    const int M = Mrows;  // 4096

    // ---- self-attention block ----
    layernorm_rows<<<M, 256>>>(hid, ln1_w, ln1_b, ln);
    gemm64<<<dim3(3 * Dn / 64, M / 64), 256>>>(ln, qkv_w, qkv_b, nullptr, qkv, M, 3 * Dn, Dn, 0);
    attn_scores<<<dim3(Tn / 64, Sn / 64, Bn * Hn), 256>>>(qkv, 3 * Dn, qkv, 3 * Dn, Dn, sc);
    softmax_rows<<<Bn * Hn * Sn, 256>>>(sc, SCALE, 1, nullptr);
    attn_ctx<<<dim3(1, Sn / 64, Bn * Hn), 256>>>(sc, qkv, 3 * Dn, 2 * Dn, ctx);
    gemm64<<<dim3(Dn / 64, M / 64), 256>>>(ctx, ao_w, ao_b, hid, hb, M, Dn, Dn, 0);

    // ---- cross-attention block ----
    layernorm_rows<<<M, 256>>>(hb, ln2_w, ln2_b, ln);
    gemm64<<<dim3(Dn / 64, M / 64), 256>>>(ln, q_w, q_b, nullptr, qb, M, Dn, Dn, 0);
    gemm64<<<dim3(2 * Dn / 64, M / 64), 256>>>(enc, kv_w, kv_b, nullptr, kvb, M, 2 * Dn, Dn, 0);
    attn_scores<<<dim3(Tn / 64, Sn / 64, Bn * Hn), 256>>>(qb, Dn, kvb, 2 * Dn, 0, sc);
    softmax_rows<<<Bn * Hn * Sn, 256>>>(sc, SCALE, 0, enc_mask);
    attn_ctx<<<dim3(1, Sn / 64, Bn * Hn), 256>>>(sc, kvb, 2 * Dn, Dn, ctx);
    gemm64<<<dim3(Dn / 64, M / 64), 256>>>(ctx, co_w, co_b, hb, hb, M, Dn, Dn, 0);

    // ---- FFN block ----
    layernorm_rows<<<M, 256>>>(hb, ln3_w, ln3_b, ln);
    gemm64<<<dim3(Fn / 64, M / 64), 256>>>(ln, fi_w, fi_b, nullptr, ffn, M, Fn, Dn, 1);
    gemm64<<<dim3(Dn / 64, M / 64), 256>>>(ffn, fo_w, fo_b, hb, out, M, Dn, Fn, 0);
}

// round 5
// speedup vs baseline: 1.8698x; 1.8698x over previous
#include <cuda_runtime.h>
#include <cuda_bf16.h>
#include <math.h>
#include <stdint.h>

// Problem constants
constexpr int Bn = 4, Sn = 1024, Tn = 1024, Dn = 1024, Fn = 4096;
constexpr int Mrows = Bn * Sn;           // 4096
constexpr float SCALE = 0.125f;          // 1/sqrt(64)

// ---------------- scratch (static device globals: allocation-free) -------------
__device__ __align__(256) float g_qkv [Mrows * 3 * Dn];        // 48 MB
__device__ __align__(256) float g_q   [Mrows * Dn];            // 16 MB
__device__ __align__(256) float g_kv  [Mrows * 2 * Dn];        // 32 MB
__device__ __align__(256) float g_h   [Mrows * Dn];            // 16 MB
__device__ __align__(256) float g_sc  [(size_t)64 * Sn * Tn];  // 256 MB scores

// split-bf16 activation buffers
__device__ __align__(256) __nv_bfloat16 g_lnh [Mrows * Dn];
__device__ __align__(256) __nv_bfloat16 g_lnl [Mrows * Dn];
__device__ __align__(256) __nv_bfloat16 g_ctxh[Mrows * Dn];
__device__ __align__(256) __nv_bfloat16 g_ctxl[Mrows * Dn];
__device__ __align__(256) __nv_bfloat16 g_ench[Mrows * Dn];
__device__ __align__(256) __nv_bfloat16 g_encl[Mrows * Dn];
__device__ __align__(256) __nv_bfloat16 g_ffnh[(size_t)Mrows * Fn];
__device__ __align__(256) __nv_bfloat16 g_ffnl[(size_t)Mrows * Fn];
// transposed split weights, one pool (16M elements)
__device__ __align__(256) __nv_bfloat16 g_wth[16 * 1024 * 1024];
__device__ __align__(256) __nv_bfloat16 g_wtl[16 * 1024 * 1024];
constexpr size_t OW_QKV = 0;
constexpr size_t OW_AO  = OW_QKV + 3u*1024*1024;
constexpr size_t OW_Q   = OW_AO  + 1u*1024*1024;
constexpr size_t OW_KV  = OW_Q   + 1u*1024*1024;
constexpr size_t OW_CO  = OW_KV  + 2u*1024*1024;
constexpr size_t OW_FI  = OW_CO  + 1u*1024*1024;
constexpr size_t OW_FO  = OW_FI  + 4u*1024*1024;

// ================= helpers ======================================================
__device__ __forceinline__ uint32_t s2u(const void* p) {
    uint32_t a;
    asm("{ .reg .u64 t; cvta.to.shared.u64 t, %1; cvt.u32.u64 %0, t; }" : "=r"(a) : "l"(p));
    return a;
}
__device__ __forceinline__ void ldsm4(uint32_t& r0, uint32_t& r1, uint32_t& r2, uint32_t& r3,
                                      uint32_t a) {
    asm volatile("ldmatrix.sync.aligned.m8n8.x4.shared.b16 {%0,%1,%2,%3}, [%4];"
        : "=r"(r0), "=r"(r1), "=r"(r2), "=r"(r3) : "r"(a));
}
__device__ __forceinline__ void mma16816(float* c, const uint32_t* a, uint32_t b0, uint32_t b1) {
    asm volatile(
        "mma.sync.aligned.m16n8k16.row.col.f32.bf16.bf16.f32 "
        "{%0,%1,%2,%3}, {%4,%5,%6,%7}, {%8,%9}, {%0,%1,%2,%3};"
        : "+f"(c[0]), "+f"(c[1]), "+f"(c[2]), "+f"(c[3])
        : "r"(a[0]), "r"(a[1]), "r"(a[2]), "r"(a[3]), "r"(b0), "r"(b1));
}
__device__ __forceinline__ void cpa16(uint32_t dst, const void* src) {
    asm volatile("cp.async.ca.shared.global [%0], [%1], 16;" :: "r"(dst), "l"(src));
}
__device__ __forceinline__ void split2(float x, __nv_bfloat16& h, __nv_bfloat16& l) {
    h = __float2bfloat16(x);
    l = __float2bfloat16(x - __bfloat162float(h));
}

// ================= tensor-core split-bf16 GEMM (mma.sync HMMA) ==================
// C[M,N] = A @ W + bias. A split (Ah,Al) [M,K] bf16; W split transposed (Bh,Bl)
// [N,K] bf16. Epilogue: +bias, opt GELU, opt residual; out fp32 and/or split bf16.
// SMEM stage (32 KB): A-block 128 rows x 128B (bytes 0-63 = Ah k-chunk, 64-127 = Al),
// then B-block same for Bh/Bl. Swizzle: 16B-chunk ^ (row&7).
__global__ __launch_bounds__(256)
void tgemm(const __nv_bfloat16* __restrict__ Ah, const __nv_bfloat16* __restrict__ Al,
           const __nv_bfloat16* __restrict__ Bh, const __nv_bfloat16* __restrict__ Bl,
           const float* __restrict__ bias, const float* __restrict__ res,
           float* __restrict__ Cf, __nv_bfloat16* __restrict__ Ch, __nv_bfloat16* __restrict__ Cl,
           int M, int N, int K, int gelu)
{
    extern __shared__ __align__(1024) char smraw[];
    const uint32_t sbase = s2u(smraw);
    const int tid = threadIdx.x, lane = tid & 31, wid = tid >> 5;
    const int m0 = blockIdx.y * 128, n0 = blockIdx.x * 128;
    const int wm = wid & 3, wn = wid >> 2;

    float acc[2][8][4] = {};

    // ---- stage one k-chunk (32 cols) into stage st ----
    auto stage = [&](int st, int k0) {
        uint32_t dst0 = sbase + st * 32768;
        #pragma unroll
        for (int p = 0; p < 8; p++) {
            int idx = tid + p * 256;          // 0..2047
            int half = idx >> 10;             // 0 = A, 1 = B
            int s = idx & 1023;
            int r = s >> 3, q = s & 7;        // row, 16B-chunk within 128B row
            const __nv_bfloat16* src;
            if (half == 0) src = ((q < 4) ? Ah : Al) + (size_t)(m0 + r) * K + k0 + (q & 3) * 8;
            else           src = ((q < 4) ? Bh : Bl) + (size_t)(n0 + r) * K + k0 + (q & 3) * 8;
            uint32_t dst = dst0 + half * 16384 + r * 128 + ((q * 16) ^ ((r & 7) * 16));
            cpa16(dst, src);
        }
        asm volatile("cp.async.commit_group;" ::: "memory");
    };

    // ---- compute one staged k-chunk ----
    auto compute = [&](int st) {
        uint32_t sA = sbase + st * 32768, sB = sA + 16384;
        #pragma unroll
        for (int ks = 0; ks < 2; ks++) {
            uint32_t ah[2][4], al[2][4];
            #pragma unroll
            for (int mt = 0; mt < 2; mt++) {
                int row = wm * 32 + mt * 16 + (lane & 15);
                int kb = ks * 32 + (lane >> 4) * 16;
                uint32_t rb = sA + row * 128;
                uint32_t xr = (row & 7) * 16;
                ldsm4(ah[mt][0], ah[mt][1], ah[mt][2], ah[mt][3], rb + (kb ^ xr));
                ldsm4(al[mt][0], al[mt][1], al[mt][2], al[mt][3], rb + ((kb + 64) ^ xr));
            }
            #pragma unroll
            for (int j = 0; j < 4; j++) {
                int g = lane >> 3;
                int row = wn * 64 + (j * 2 + (g >> 1)) * 8 + (lane & 7);
                int kb = ks * 32 + (g & 1) * 16;
                uint32_t rb = sB + row * 128;
                uint32_t xr = (row & 7) * 16;
                uint32_t bh[4], bl[4];
                ldsm4(bh[0], bh[1], bh[2], bh[3], rb + (kb ^ xr));
                ldsm4(bl[0], bl[1], bl[2], bl[3], rb + ((kb + 64) ^ xr));
                #pragma unroll
                for (int mt = 0; mt < 2; mt++) {
                    #pragma unroll
                    for (int t = 0; t < 2; t++) {
                        float* c = acc[mt][j * 2 + t];
                        mma16816(c, ah[mt], bh[2 * t], bh[2 * t + 1]);
                        mma16816(c, ah[mt], bl[2 * t], bl[2 * t + 1]);
                        mma16816(c, al[mt], bh[2 * t], bh[2 * t + 1]);
                    }
                }
            }
        }
    };

    const int NC = K >> 5;
    stage(0, 0);
    for (int c = 0; c < NC; c++) {
        asm volatile("cp.async.wait_group 0;" ::: "memory");
        __syncthreads();
        if (c + 1 < NC) stage((c + 1) & 1, (c + 1) * 32);
        compute(c & 1);
    }

    // ---- epilogue ----
    const int r_in = lane >> 2, c_in = (lane & 3) * 2;
    #pragma unroll
    for (int mt = 0; mt < 2; mt++) {
        #pragma unroll
        for (int rr = 0; rr < 2; rr++) {
            int row = m0 + wm * 32 + mt * 16 + rr * 8 + r_in;
            #pragma unroll
            for (int nt = 0; nt < 8; nt++) {
                int col = n0 + wn * 64 + nt * 8 + c_in;
                float v0 = acc[mt][nt][rr * 2 + 0] + bias[col];
                float v1 = acc[mt][nt][rr * 2 + 1] + bias[col + 1];
                if (gelu) {
                    v0 = 0.5f * v0 * (1.0f + erff(v0 * 0.7071067811865476f));
                    v1 = 0.5f * v1 * (1.0f + erff(v1 * 0.7071067811865476f));
                }
                if (res) {
                    float2 rr2 = *(const float2*)(res + (size_t)row * N + col);
                    v0 += rr2.x; v1 += rr2.y;
                }
                if (Cf) *(float2*)(Cf + (size_t)row * N + col) = make_float2(v0, v1);
                if (Ch) {
                    __nv_bfloat16 h0, l0, h1, l1;
                    split2(v0, h0, l0); split2(v1, h1, l1);
                    *(__nv_bfloat162*)(Ch + (size_t)row * N + col) = __nv_bfloat162(h0, h1);
                    *(__nv_bfloat162*)(Cl + (size_t)row * N + col) = __nv_bfloat162(l0, l1);
                }
            }
        }
    }
}

// ============== weight transpose + split: W[K,N] -> Wh/Wl[N,K] bf16 =============
__global__ __launch_bounds__(256) void wsplitT(
    const float* __restrict__ W, __nv_bfloat16* __restrict__ oh,
    __nv_bfloat16* __restrict__ ol, int K, int N)
{
    __shared__ float t[32][33];
    int tx = threadIdx.x & 31, ty = threadIdx.x >> 5;
    int n0 = blockIdx.x * 32, k0 = blockIdx.y * 32;
    #pragma unroll
    for (int i = 0; i < 4; i++)
        t[ty + i * 8][tx] = W[(size_t)(k0 + ty + i * 8) * N + n0 + tx];
    __syncthreads();
    #pragma unroll
    for (int i = 0; i < 4; i++) {
        float v = t[tx][ty + i * 8];
        __nv_bfloat16 h, l;
        split2(v, h, l);
        size_t o = (size_t)(n0 + ty + i * 8) * K + k0 + tx;
        oh[o] = h; ol[o] = l;
    }
}

// ============== elementwise split (enc hidden states) ===========================
__global__ __launch_bounds__(256) void esplit(
    const float* __restrict__ x, __nv_bfloat16* __restrict__ oh,
    __nv_bfloat16* __restrict__ ol)
{
    int i = blockIdx.x * 256 + threadIdx.x;
    float4 v = ((const float4*)x)[i];
    __nv_bfloat16 h0, l0, h1, l1, h2, l2, h3, l3;
    split2(v.x, h0, l0); split2(v.y, h1, l1); split2(v.z, h2, l2); split2(v.w, h3, l3);
    ((__nv_bfloat162*)oh)[2 * i]     = __nv_bfloat162(h0, h1);
    ((__nv_bfloat162*)oh)[2 * i + 1] = __nv_bfloat162(h2, h3);
    ((__nv_bfloat162*)ol)[2 * i]     = __nv_bfloat162(l0, l1);
    ((__nv_bfloat162*)ol)[2 * i + 1] = __nv_bfloat162(l2, l3);
}

// ============== LayerNorm -> split bf16 =========================================
__global__ __launch_bounds__(256) void ln_split(
    const float* __restrict__ x, const float* __restrict__ w,
    const float* __restrict__ bb, __nv_bfloat16* __restrict__ yh,
    __nv_bfloat16* __restrict__ yl)
{
    const int row = blockIdx.x, tid = threadIdx.x;
    float4 v = ((const float4*)(x + (size_t)row * Dn))[tid];
    float s  = v.x + v.y + v.z + v.w;
    float sq = v.x * v.x + v.y * v.y + v.z * v.z + v.w * v.w;

    __shared__ float sm[18];
    #pragma unroll
    for (int off = 16; off > 0; off >>= 1) {
        s  += __shfl_xor_sync(~0u, s,  off);
        sq += __shfl_xor_sync(~0u, sq, off);
    }
    if ((tid & 31) == 0) { sm[tid >> 5] = s; sm[(tid >> 5) + 8] = sq; }
    __syncthreads();
    if (tid < 32) {
        float a  = (tid < 8) ? sm[tid]     : 0.f;
        float aq = (tid < 8) ? sm[tid + 8] : 0.f;
        #pragma unroll
        for (int off = 4; off > 0; off >>= 1) {
            a  += __shfl_xor_sync(~0u, a,  off);
            aq += __shfl_xor_sync(~0u, aq, off);
        }
        if (tid == 0) { sm[16] = a; sm[17] = aq; }
    }
    __syncthreads();
    const float mean = sm[16] * (1.0f / Dn);
    const float var  = sm[17] * (1.0f / Dn) - mean * mean;
    const float rstd = rsqrtf(var + 1e-12f);

    float4 w4 = ((const float4*)w)[tid];
    float4 b4 = ((const float4*)bb)[tid];
    float o0 = w4.x * (v.x - mean) * rstd + b4.x;
    float o1 = w4.y * (v.y - mean) * rstd + b4.y;
    float o2 = w4.z * (v.z - mean) * rstd + b4.z;
    float o3 = w4.w * (v.w - mean) * rstd + b4.w;
    __nv_bfloat16 h0, l0, h1, l1, h2, l2, h3, l3;
    split2(o0, h0, l0); split2(o1, h1, l1); split2(o2, h2, l2); split2(o3, h3, l3);
    size_t base = (size_t)row * Dn + tid * 4;
    ((__nv_bfloat162*)(yh + base))[0] = __nv_bfloat162(h0, h1);
    ((__nv_bfloat162*)(yh + base))[1] = __nv_bfloat162(h2, h3);
    ((__nv_bfloat162*)(yl + base))[0] = __nv_bfloat162(l0, l1);
    ((__nv_bfloat162*)(yl + base))[1] = __nv_bfloat162(l2, l3);
}

// ================= SIMT attention =======================================
#define MICRO_FMA(a, b)                                                              \
    acc[0][0] += a.x * b.x; acc[0][1] += a.x * b.y; acc[0][2] += a.x * b.z; acc[0][3] += a.x * b.w; \
    acc[1][0] += a.y * b.x; acc[1][1] += a.y * b.y; acc[1][2] += a.y * b.z; acc[1][3] += a.y * b.w; \
    acc[2][0] += a.z * b.x; acc[2][1] += a.z * b.y; acc[2][2] += a.z * b.z; acc[2][3] += a.z * b.w; \
    acc[3][0] += a.w * b.x; acc[3][1] += a.w * b.y; acc[3][2] += a.w * b.z; acc[3][3] += a.w * b.w;

__global__ __launch_bounds__(256) void attn_scores(
    const float* __restrict__ qbase, int ldq,
    const float* __restrict__ kbase, int ldk, int koff,
    float* __restrict__ sc)
{
    __shared__ __align__(16) float Qs[64][68];
    __shared__ __align__(16) float Ks[64][68];
    const int z = blockIdx.z, b = z >> 4, h = z & 15;
    const int t0 = blockIdx.x * 64, s0 = blockIdx.y * 64;
    const float* Qp = qbase + (size_t)b * Sn * ldq + h * 64;
    const float* Kp = kbase + (size_t)b * Tn * ldk + koff + h * 64;

    const int tid = threadIdx.x;
    const int d = tid & 63, r = tid >> 6;
    #pragma unroll
    for (int i = 0; i < 16; i++) {
        Qs[d][r + i * 4] = Qp[(size_t)(s0 + r + i * 4) * ldq + d];
        Ks[d][r + i * 4] = Kp[(size_t)(t0 + r + i * 4) * ldk + d];
    }
    __syncthreads();

    const int tx = tid & 15, ty = tid >> 4;
    float acc[4][4] = {};
    #pragma unroll 16
    for (int kk = 0; kk < 64; kk++) {
        float4 a = *(const float4*)&Qs[kk][ty * 4];
        float4 b4 = *(const float4*)&Ks[kk][tx * 4];
        MICRO_FMA(a, b4)
    }

    float* out = sc + ((size_t)z * Sn + s0) * Tn + t0;
    #pragma unroll
    for (int i = 0; i < 4; i++)
        #pragma unroll
        for (int j = 0; j < 4; j++)
            out[(size_t)(ty * 4 + i) * Tn + tx * 4 + j] = acc[i][j];
}

__global__ __launch_bounds__(256) void softmax_rows(
    float* __restrict__ sc, float scale, int causal, const float* __restrict__ addmask)
{
    const int row = blockIdx.x;
    const int s = row & (Sn - 1);
    const int b = row >> 14;
    float* p = sc + (size_t)row * Tn;
    const int tid = threadIdx.x;

    float vals[4];
    float mx = -1e30f;
    #pragma unroll
    for (int i = 0; i < 4; i++) {
        int c = tid + i * 256;
        float v = p[c] * scale;
        if (causal) { if (c > s) v = -10000.0f; }
        else if (addmask) v += addmask[(size_t)b * Tn + c];
        vals[i] = v;
        mx = fmaxf(mx, v);
    }
    __shared__ float sm[18];
    #pragma unroll
    for (int off = 16; off > 0; off >>= 1) mx = fmaxf(mx, __shfl_xor_sync(~0u, mx, off));
    if ((tid & 31) == 0) sm[tid >> 5] = mx;
    __syncthreads();
    if (tid < 32) {
        float a = (tid < 8) ? sm[tid] : -1e30f;
        #pragma unroll
        for (int off = 4; off > 0; off >>= 1) a = fmaxf(a, __shfl_xor_sync(~0u, a, off));
        if (tid == 0) sm[16] = a;
    }
    __syncthreads();
    const float m = sm[16];

    float sum = 0.f;
    #pragma unroll
    for (int i = 0; i < 4; i++) { vals[i] = expf(vals[i] - m); sum += vals[i]; }
    #pragma unroll
    for (int off = 16; off > 0; off >>= 1) sum += __shfl_xor_sync(~0u, sum, off);
    if ((tid & 31) == 0) sm[tid >> 5] = sum;
    __syncthreads();
    if (tid < 32) {
        float a = (tid < 8) ? sm[tid] : 0.f;
        #pragma unroll
        for (int off = 4; off > 0; off >>= 1) a += __shfl_xor_sync(~0u, a, off);
        if (tid == 0) sm[17] = a;
    }
    __syncthreads();
    const float inv = 1.0f / sm[17];
    #pragma unroll
    for (int i = 0; i < 4; i++) p[tid + i * 256] = vals[i] * inv;
}

// ctx writes split bf16 directly (feeds tensor GEMM)
__global__ __launch_bounds__(256) void attn_ctx(
    const float* __restrict__ sc,
    const float* __restrict__ vbase, int ldv, int voff,
    __nv_bfloat16* __restrict__ ctxh, __nv_bfloat16* __restrict__ ctxl)
{
    __shared__ __align__(16) float Ps[16][68];
    __shared__ __align__(16) float Vs[16][68];
    const int z = blockIdx.z, b = z >> 4, h = z & 15;
    const int s0 = blockIdx.y * 64;
    const float* Pp = sc + ((size_t)z * Sn + s0) * Tn;
    const float* Vp = vbase + (size_t)b * Tn * ldv + voff + h * 64;

    const int tid = threadIdx.x;
    const int kp = tid & 15, rp = tid >> 4;
    const int nv = tid & 63, kv = tid >> 6;
    const int tx = tid & 15, ty = tid >> 4;

    float acc[4][4] = {};
    for (int kt = 0; kt < Tn; kt += 16) {
        #pragma unroll
        for (int i = 0; i < 4; i++)
            Ps[kp][rp + i * 16] = Pp[(size_t)(rp + i * 16) * Tn + kt + kp];
        #pragma unroll
        for (int i = 0; i < 4; i++)
            Vs[kv + i * 4][nv] = Vp[(size_t)(kt + kv + i * 4) * ldv + nv];
        __syncthreads();
        #pragma unroll
        for (int kk = 0; kk < 16; kk++) {
            float4 a = *(const float4*)&Ps[kk][ty * 4];
            float4 b4 = *(const float4*)&Vs[kk][tx * 4];
            MICRO_FMA(a, b4)
        }
        __syncthreads();
    }

    size_t base = (size_t)(b * Sn + s0) * Dn + h * 64;
    #pragma unroll
    for (int i = 0; i < 4; i++)
        #pragma unroll
        for (int j = 0; j < 4; j++) {
            __nv_bfloat16 hh, ll;
            split2(acc[i][j], hh, ll);
            size_t o = base + (size_t)(ty * 4 + i) * Dn + tx * 4 + j;
            ctxh[o] = hh; ctxl[o] = ll;
        }
}

// -------------------------------- launcher --------------------------------------
extern "C" void kernel_launch(void* const* d_in, const int* in_sizes, int n_in,
                              void* d_out, int out_size)
{
    const float* hid      = (const float*)d_in[0];
    const float* enc      = (const float*)d_in[1];
    const float* enc_mask = (const float*)d_in[2];
    const float *ln1_w = (const float*)d_in[4],  *ln1_b = (const float*)d_in[5];
    const float *qkv_w = (const float*)d_in[6],  *qkv_b = (const float*)d_in[7];
    const float *ao_w  = (const float*)d_in[8],  *ao_b  = (const float*)d_in[9];
    const float *ln2_w = (const float*)d_in[10], *ln2_b = (const float*)d_in[11];
    const float *q_w   = (const float*)d_in[12], *q_b   = (const float*)d_in[13];
    const float *kv_w  = (const float*)d_in[14], *kv_b  = (const float*)d_in[15];
    const float *co_w  = (const float*)d_in[16], *co_b  = (const float*)d_in[17];
    const float *ln3_w = (const float*)d_in[18], *ln3_b = (const float*)d_in[19];
    const float *fi_w  = (const float*)d_in[20], *fi_b  = (const float*)d_in[21];
    const float *fo_w  = (const float*)d_in[22], *fo_b  = (const float*)d_in[23];
    float* out = (float*)d_out;

    float *qkv, *qb, *kvb, *hb, *sc;
    __nv_bfloat16 *lnh, *lnl, *ctxh, *ctxl, *ench, *encl, *ffnh, *ffnl, *wth, *wtl;
    cudaGetSymbolAddress((void**)&qkv, g_qkv);
    cudaGetSymbolAddress((void**)&qb,  g_q);
    cudaGetSymbolAddress((void**)&kvb, g_kv);
    cudaGetSymbolAddress((void**)&hb,  g_h);
    cudaGetSymbolAddress((void**)&sc,  g_sc);
    cudaGetSymbolAddress((void**)&lnh, g_lnh);
    cudaGetSymbolAddress((void**)&lnl, g_lnl);
    cudaGetSymbolAddress((void**)&ctxh, g_ctxh);
    cudaGetSymbolAddress((void**)&ctxl, g_ctxl);
    cudaGetSymbolAddress((void**)&ench, g_ench);
    cudaGetSymbolAddress((void**)&encl, g_encl);
    cudaGetSymbolAddress((void**)&ffnh, g_ffnh);
    cudaGetSymbolAddress((void**)&ffnl, g_ffnl);
    cudaGetSymbolAddress((void**)&wth, g_wth);
    cudaGetSymbolAddress((void**)&wtl, g_wtl);

    static bool attr_done = false;
    if (!attr_done) {
        cudaFuncSetAttribute(tgemm, cudaFuncAttributeMaxDynamicSharedMemorySize, 65536);
        attr_done = true;
    }
    const int SMEM = 65536;
    const int M = Mrows;  // 4096

    // ---- weight conversion (transpose + split) ----
    wsplitT<<<dim3(3072 / 32, 1024 / 32), 256>>>(qkv_w, wth + OW_QKV, wtl + OW_QKV, 1024, 3072);
    wsplitT<<<dim3(1024 / 32, 1024 / 32), 256>>>(ao_w,  wth + OW_AO,  wtl + OW_AO,  1024, 1024);
    wsplitT<<<dim3(1024 / 32, 1024 / 32), 256>>>(q_w,   wth + OW_Q,   wtl + OW_Q,   1024, 1024);
    wsplitT<<<dim3(2048 / 32, 1024 / 32), 256>>>(kv_w,  wth + OW_KV,  wtl + OW_KV,  1024, 2048);
    wsplitT<<<dim3(1024 / 32, 1024 / 32), 256>>>(co_w,  wth + OW_CO,  wtl + OW_CO,  1024, 1024);
    wsplitT<<<dim3(4096 / 32, 1024 / 32), 256>>>(fi_w,  wth + OW_FI,  wtl + OW_FI,  1024, 4096);
    wsplitT<<<dim3(1024 / 32, 4096 / 32), 256>>>(fo_w,  wth + OW_FO,  wtl + OW_FO,  4096, 1024);
    esplit<<<(M * Dn / 4) / 256, 256>>>(enc, ench, encl);

    // ---- self-attention block ----
    ln_split<<<M, 256>>>(hid, ln1_w, ln1_b, lnh, lnl);
    tgemm<<<dim3(3072 / 128, M / 128), 256, SMEM>>>(lnh, lnl, wth + OW_QKV, wtl + OW_QKV,
        qkv_b, nullptr, qkv, nullptr, nullptr, M, 3072, 1024, 0);
    attn_scores<<<dim3(Tn / 64, Sn / 64, 64), 256>>>(qkv, 3 * Dn, qkv, 3 * Dn, Dn, sc);
    softmax_rows<<<64 * Sn, 256>>>(sc, SCALE, 1, nullptr);
    attn_ctx<<<dim3(1, Sn / 64, 64), 256>>>(sc, qkv, 3 * Dn, 2 * Dn, ctxh, ctxl);
    tgemm<<<dim3(1024 / 128, M / 128), 256, SMEM>>>(ctxh, ctxl, wth + OW_AO, wtl + OW_AO,
        ao_b, hid, hb, nullptr, nullptr, M, 1024, 1024, 0);

    // ---- cross-attention block ----
    ln_split<<<M, 256>>>(hb, ln2_w, ln2_b, lnh, lnl);
    tgemm<<<dim3(1024 / 128, M / 128), 256, SMEM>>>(lnh, lnl, wth + OW_Q, wtl + OW_Q,
        q_b, nullptr, qb, nullptr, nullptr, M, 1024, 1024, 0);
    tgemm<<<dim3(2048 / 128, M / 128), 256, SMEM>>>(ench, encl, wth + OW_KV, wtl + OW_KV,
        kv_b, nullptr, kvb, nullptr, nullptr, M, 2048, 1024, 0);
    attn_scores<<<dim3(Tn / 64, Sn / 64, 64), 256>>>(qb, Dn, kvb, 2 * Dn, 0, sc);
    softmax_rows<<<64 * Sn, 256>>>(sc, SCALE, 0, enc_mask);
    attn_ctx<<<dim3(1, Sn / 64, 64), 256>>>(sc, kvb, 2 * Dn, Dn, ctxh, ctxl);
    tgemm<<<dim3(1024 / 128, M / 128), 256, SMEM>>>(ctxh, ctxl, wth + OW_CO, wtl + OW_CO,
        co_b, hb, hb, nullptr, nullptr, M, 1024, 1024, 0);

    // ---- FFN block ----
    ln_split<<<M, 256>>>(hb, ln3_w, ln3_b, lnh, lnl);
    tgemm<<<dim3(4096 / 128, M / 128), 256, SMEM>>>(lnh, lnl, wth + OW_FI, wtl + OW_FI,
        fi_b, nullptr, nullptr, ffnh, ffnl, M, 4096, 1024, 1);
    tgemm<<<dim3(1024 / 128, M / 128), 256, SMEM>>>(ffnh, ffnl, wth + OW_FO, wtl + OW_FO,
        fo_b, hb, out, nullptr, nullptr, M, 1024, 4096, 0);
}

// round 7
// speedup vs baseline: 2.3666x; 1.2657x over previous
#include <cuda_runtime.h>
#include <cuda_bf16.h>
#include <math.h>
#include <stdint.h>

// Problem constants
constexpr int Bn = 4, Sn = 1024, Tn = 1024, Dn = 1024, Fn = 4096;
constexpr int Mrows = Bn * Sn;           // 4096
constexpr float SCALE = 0.125f;          // 1/sqrt(64)

// ---------------- scratch (static device globals: allocation-free) -------------
__device__ __align__(256) float g_sc [(size_t)64 * Sn * Tn];   // 256 MB scores
__device__ __align__(256) float g_h  [Mrows * Dn];             // fp32 hidden

__device__ __align__(256) __nv_bfloat16 g_qkvh[Mrows * 3 * Dn];
__device__ __align__(256) __nv_bfloat16 g_qkvl[Mrows * 3 * Dn];
__device__ __align__(256) __nv_bfloat16 g_qh  [Mrows * Dn];
__device__ __align__(256) __nv_bfloat16 g_ql  [Mrows * Dn];
__device__ __align__(256) __nv_bfloat16 g_kvh [Mrows * 2 * Dn];
__device__ __align__(256) __nv_bfloat16 g_kvl [Mrows * 2 * Dn];
__device__ __align__(256) __nv_bfloat16 g_ph  [(size_t)64 * Sn * Tn];
__device__ __align__(256) __nv_bfloat16 g_pl  [(size_t)64 * Sn * Tn];
__device__ __align__(256) __nv_bfloat16 g_vth [64 * 64 * 1024];
__device__ __align__(256) __nv_bfloat16 g_vtl [64 * 64 * 1024];

__device__ __align__(256) __nv_bfloat16 g_lnh [Mrows * Dn];
__device__ __align__(256) __nv_bfloat16 g_lnl [Mrows * Dn];
__device__ __align__(256) __nv_bfloat16 g_ctxh[Mrows * Dn];
__device__ __align__(256) __nv_bfloat16 g_ctxl[Mrows * Dn];
__device__ __align__(256) __nv_bfloat16 g_ench[Mrows * Dn];
__device__ __align__(256) __nv_bfloat16 g_encl[Mrows * Dn];
__device__ __align__(256) __nv_bfloat16 g_ffnh[(size_t)Mrows * Fn];
__device__ __align__(256) __nv_bfloat16 g_ffnl[(size_t)Mrows * Fn];
__device__ __align__(256) __nv_bfloat16 g_wth[16 * 1024 * 1024];
__device__ __align__(256) __nv_bfloat16 g_wtl[16 * 1024 * 1024];
constexpr size_t OW_QKV = 0;
constexpr size_t OW_AO  = OW_QKV + 3u*1024*1024;
constexpr size_t OW_Q   = OW_AO  + 1u*1024*1024;
constexpr size_t OW_KV  = OW_Q   + 1u*1024*1024;
constexpr size_t OW_CO  = OW_KV  + 2u*1024*1024;
constexpr size_t OW_FI  = OW_CO  + 1u*1024*1024;
constexpr size_t OW_FO  = OW_FI  + 4u*1024*1024;

// ================= helpers ======================================================
__device__ __forceinline__ uint32_t s2u(const void* p) {
    uint32_t a;
    asm("{ .reg .u64 t; cvta.to.shared.u64 t, %1; cvt.u32.u64 %0, t; }" : "=r"(a) : "l"(p));
    return a;
}
__device__ __forceinline__ void ldsm4(uint32_t& r0, uint32_t& r1, uint32_t& r2, uint32_t& r3,
                                      uint32_t a) {
    asm volatile("ldmatrix.sync.aligned.m8n8.x4.shared.b16 {%0,%1,%2,%3}, [%4];"
        : "=r"(r0), "=r"(r1), "=r"(r2), "=r"(r3) : "r"(a));
}
__device__ __forceinline__ void mma16816(float* c, const uint32_t* a, uint32_t b0, uint32_t b1) {
    asm volatile(
        "mma.sync.aligned.m16n8k16.row.col.f32.bf16.bf16.f32 "
        "{%0,%1,%2,%3}, {%4,%5,%6,%7}, {%8,%9}, {%0,%1,%2,%3};"
        : "+f"(c[0]), "+f"(c[1]), "+f"(c[2]), "+f"(c[3])
        : "r"(a[0]), "r"(a[1]), "r"(a[2]), "r"(a[3]), "r"(b0), "r"(b1));
}
__device__ __forceinline__ void cpa16(uint32_t dst, const void* src) {
    asm volatile("cp.async.ca.shared.global [%0], [%1], 16;" :: "r"(dst), "l"(src));
}
__device__ __forceinline__ void split2(float x, __nv_bfloat16& h, __nv_bfloat16& l) {
    h = __float2bfloat16(x);
    l = __float2bfloat16(x - __bfloat162float(h));
}

// ================= tensor-core split-bf16 GEMM (mma.sync HMMA) ==================
// Batched: z = blockIdx.z, b=z>>4, h=z&15; operand offset = b*sXb + h*sXh.
// A split [*,K] (row stride lda), B split [N,K] (row stride ldb), both K-major.
// C = A@B^T (+bias)(+GELU)(+res); outputs fp32 (Cf) and/or split bf16 (Ch/Cl).
template<int BN>
__global__ __launch_bounds__(256)
void tgemm(const __nv_bfloat16* __restrict__ Ah_, const __nv_bfloat16* __restrict__ Al_,
           int lda, size_t sAb, size_t sAh,
           const __nv_bfloat16* __restrict__ Bh_, const __nv_bfloat16* __restrict__ Bl_,
           int ldb, size_t sBb, size_t sBh,
           const float* __restrict__ bias, const float* __restrict__ res,
           float* __restrict__ Cf, __nv_bfloat16* __restrict__ Ch, __nv_bfloat16* __restrict__ Cl,
           int ldc, size_t sCb, size_t sCh,
           int K, int gelu)
{
    constexpr int STAGE = 16384 + BN * 128;      // bytes per pipeline stage
    constexpr int LP    = (128 + BN) * 8 / 256;  // 16B loads per thread per stage
    constexpr int NTC   = BN / 16;               // 8-col n-tiles per warp
    constexpr int NJ    = BN / 32;               // ldsm-b iterations

    extern __shared__ __align__(1024) char smraw[];
    const uint32_t sbase = s2u(smraw);
    const int tid = threadIdx.x, lane = tid & 31, wid = tid >> 5;
    const int z = blockIdx.z, zb = z >> 4, zh = z & 15;
    const int m0 = blockIdx.y * 128, n0 = blockIdx.x * BN;
    const int wm = wid & 3, wn = wid >> 2;

    const __nv_bfloat16* Ahp = Ah_ + zb * sAb + zh * sAh + (size_t)m0 * lda;
    const __nv_bfloat16* Alp = Al_ + zb * sAb + zh * sAh + (size_t)m0 * lda;
    const __nv_bfloat16* Bhp = Bh_ + zb * sBb + zh * sBh + (size_t)n0 * ldb;
    const __nv_bfloat16* Blp = Bl_ + zb * sBb + zh * sBh + (size_t)n0 * ldb;
    const size_t coff = zb * sCb + zh * sCh;

    float acc[2][NTC][4] = {};

    auto stage = [&](int st, int k0) {
        uint32_t dst0 = sbase + st * STAGE;
        #pragma unroll
        for (int p = 0; p < LP; p++) {
            int idx = tid + p * 256;
            int isB = idx >= 1024;
            int s = isB ? idx - 1024 : idx;
            int r = s >> 3, q = s & 7;
            const __nv_bfloat16* src = isB
                ? ((q < 4 ? Bhp : Blp) + (size_t)r * ldb + k0 + (q & 3) * 8)
                : ((q < 4 ? Ahp : Alp) + (size_t)r * lda + k0 + (q & 3) * 8);
            uint32_t dst = dst0 + isB * 16384 + r * 128 + ((q * 16) ^ ((r & 7) * 16));
            cpa16(dst, src);
        }
        asm volatile("cp.async.commit_group;" ::: "memory");
    };

    auto compute = [&](int st) {
        uint32_t sA = sbase + st * STAGE, sB = sA + 16384;
        #pragma unroll
        for (int ks = 0; ks < 2; ks++) {
            uint32_t ah[2][4], al[2][4];
            #pragma unroll
            for (int mt = 0; mt < 2; mt++) {
                int row = wm * 32 + mt * 16 + (lane & 15);
                int kb = ks * 32 + (lane >> 4) * 16;
                uint32_t rb = sA + row * 128;
                uint32_t xr = (row & 7) * 16;
                ldsm4(ah[mt][0], ah[mt][1], ah[mt][2], ah[mt][3], rb + (kb ^ xr));
                ldsm4(al[mt][0], al[mt][1], al[mt][2], al[mt][3], rb + ((kb + 64) ^ xr));
            }
            #pragma unroll
            for (int j = 0; j < NJ; j++) {
                int g = lane >> 3;
                int row = wn * (BN / 2) + (j * 2 + (g >> 1)) * 8 + (lane & 7);
                int kb = ks * 32 + (g & 1) * 16;
                uint32_t rb = sB + row * 128;
                uint32_t xr = (row & 7) * 16;
                uint32_t bh[4], bl[4];
                ldsm4(bh[0], bh[1], bh[2], bh[3], rb + (kb ^ xr));
                ldsm4(bl[0], bl[1], bl[2], bl[3], rb + ((kb + 64) ^ xr));
                #pragma unroll
                for (int mt = 0; mt < 2; mt++) {
                    #pragma unroll
                    for (int t = 0; t < 2; t++) {
                        float* c = acc[mt][j * 2 + t];
                        mma16816(c, ah[mt], bh[2 * t], bh[2 * t + 1]);
                        mma16816(c, ah[mt], bl[2 * t], bl[2 * t + 1]);
                        mma16816(c, al[mt], bh[2 * t], bh[2 * t + 1]);
                    }
                }
            }
        }
    };

    const int NC = K >> 5;
    stage(0, 0);
    for (int c = 0; c < NC; c++) {
        asm volatile("cp.async.wait_group 0;" ::: "memory");
        __syncthreads();
        if (c + 1 < NC) stage((c + 1) & 1, (c + 1) * 32);
        compute(c & 1);
    }

    // ---- epilogue ----
    const int r_in = lane >> 2, c_in = (lane & 3) * 2;
    #pragma unroll
    for (int mt = 0; mt < 2; mt++) {
        #pragma unroll
        for (int rr = 0; rr < 2; rr++) {
            int row = m0 + wm * 32 + mt * 16 + rr * 8 + r_in;
            #pragma unroll
            for (int nt = 0; nt < NTC; nt++) {
                int col = n0 + wn * (BN / 2) + nt * 8 + c_in;
                float v0 = acc[mt][nt][rr * 2 + 0];
                float v1 = acc[mt][nt][rr * 2 + 1];
                if (bias) { v0 += bias[col]; v1 += bias[col + 1]; }
                if (gelu) {
                    v0 = 0.5f * v0 * (1.0f + erff(v0 * 0.7071067811865476f));
                    v1 = 0.5f * v1 * (1.0f + erff(v1 * 0.7071067811865476f));
                }
                size_t off = coff + (size_t)row * ldc + col;
                if (res) {
                    float2 rr2 = *(const float2*)(res + off);
                    v0 += rr2.x; v1 += rr2.y;
                }
                if (Cf) *(float2*)(Cf + off) = make_float2(v0, v1);
                if (Ch) {
                    __nv_bfloat16 h0, l0, h1, l1;
                    split2(v0, h0, l0); split2(v1, h1, l1);
                    *(__nv_bfloat162*)(Ch + off) = __nv_bfloat162(h0, h1);
                    *(__nv_bfloat162*)(Cl + off) = __nv_bfloat162(l0, l1);
                }
            }
        }
    }
}

// ============== V transpose: vt[z][d][t] = v[(b*S+t)*ld + off + h*64 + d] =======
__global__ __launch_bounds__(256) void vtransT(
    const __nv_bfloat16* __restrict__ inh, const __nv_bfloat16* __restrict__ inl,
    int ld, int off, __nv_bfloat16* __restrict__ oth, __nv_bfloat16* __restrict__ otl)
{
    __shared__ __nv_bfloat16 th[32][33], tl[32][33];
    const int z = blockIdx.z, b = z >> 4, h = z & 15;
    const int t0 = blockIdx.x * 32, d0 = blockIdx.y * 32;
    const int tx = threadIdx.x & 31, ty = threadIdx.x >> 5;
    const __nv_bfloat16* sh = inh + (size_t)b * Sn * ld + off + h * 64 + d0;
    const __nv_bfloat16* sl = inl + (size_t)b * Sn * ld + off + h * 64 + d0;
    #pragma unroll
    for (int i = 0; i < 4; i++) {
        int t = t0 + ty + i * 8;
        th[ty + i * 8][tx] = sh[(size_t)t * ld + tx];
        tl[ty + i * 8][tx] = sl[(size_t)t * ld + tx];
    }
    __syncthreads();
    size_t obase = (size_t)z * 64 * 1024;
    #pragma unroll
    for (int i = 0; i < 4; i++) {
        int d = d0 + ty + i * 8;
        oth[obase + (size_t)d * 1024 + t0 + tx] = th[tx][ty + i * 8];
        otl[obase + (size_t)d * 1024 + t0 + tx] = tl[tx][ty + i * 8];
    }
}

// ============== weight transpose + split: W[K,N] -> Wh/Wl[N,K] bf16 =============
__global__ __launch_bounds__(256) void wsplitT(
    const float* __restrict__ W, __nv_bfloat16* __restrict__ oh,
    __nv_bfloat16* __restrict__ ol, int K, int N)
{
    __shared__ float t[32][33];
    int tx = threadIdx.x & 31, ty = threadIdx.x >> 5;
    int n0 = blockIdx.x * 32, k0 = blockIdx.y * 32;
    #pragma unroll
    for (int i = 0; i < 4; i++)
        t[ty + i * 8][tx] = W[(size_t)(k0 + ty + i * 8) * N + n0 + tx];
    __syncthreads();
    #pragma unroll
    for (int i = 0; i < 4; i++) {
        float v = t[tx][ty + i * 8];
        __nv_bfloat16 h, l;
        split2(v, h, l);
        size_t o = (size_t)(n0 + ty + i * 8) * K + k0 + tx;
        oh[o] = h; ol[o] = l;
    }
}

// ============== elementwise split (enc hidden states) ===========================
__global__ __launch_bounds__(256) void esplit(
    const float* __restrict__ x, __nv_bfloat16* __restrict__ oh,
    __nv_bfloat16* __restrict__ ol)
{
    int i = blockIdx.x * 256 + threadIdx.x;
    float4 v = ((const float4*)x)[i];
    __nv_bfloat16 h0, l0, h1, l1, h2, l2, h3, l3;
    split2(v.x, h0, l0); split2(v.y, h1, l1); split2(v.z, h2, l2); split2(v.w, h3, l3);
    ((__nv_bfloat162*)oh)[2 * i]     = __nv_bfloat162(h0, h1);
    ((__nv_bfloat162*)oh)[2 * i + 1] = __nv_bfloat162(h2, h3);
    ((__nv_bfloat162*)ol)[2 * i]     = __nv_bfloat162(l0, l1);
    ((__nv_bfloat162*)ol)[2 * i + 1] = __nv_bfloat162(l2, l3);
}

// ============== LayerNorm -> split bf16 =========================================
__global__ __launch_bounds__(256) void ln_split(
    const float* __restrict__ x, const float* __restrict__ w,
    const float* __restrict__ bb, __nv_bfloat16* __restrict__ yh,
    __nv_bfloat16* __restrict__ yl)
{
    const int row = blockIdx.x, tid = threadIdx.x;
    float4 v = ((const float4*)(x + (size_t)row * Dn))[tid];
    float s  = v.x + v.y + v.z + v.w;
    float sq = v.x * v.x + v.y * v.y + v.z * v.z + v.w * v.w;

    __shared__ float sm[18];
    #pragma unroll
    for (int off = 16; off > 0; off >>= 1) {
        s  += __shfl_xor_sync(~0u, s,  off);
        sq += __shfl_xor_sync(~0u, sq, off);
    }
    if ((tid & 31) == 0) { sm[tid >> 5] = s; sm[(tid >> 5) + 8] = sq; }
    __syncthreads();
    if (tid < 32) {
        float a  = (tid < 8) ? sm[tid]     : 0.f;
        float aq = (tid < 8) ? sm[tid + 8] : 0.f;
        #pragma unroll
        for (int off = 4; off > 0; off >>= 1) {
            a  += __shfl_xor_sync(~0u, a,  off);
            aq += __shfl_xor_sync(~0u, aq, off);
        }
        if (tid == 0) { sm[16] = a; sm[17] = aq; }
    }
    __syncthreads();
    const float mean = sm[16] * (1.0f / Dn);
    const float var  = sm[17] * (1.0f / Dn) - mean * mean;
    const float rstd = rsqrtf(var + 1e-12f);

    float4 w4 = ((const float4*)w)[tid];
    float4 b4 = ((const float4*)bb)[tid];
    float o0 = w4.x * (v.x - mean) * rstd + b4.x;
    float o1 = w4.y * (v.y - mean) * rstd + b4.y;
    float o2 = w4.z * (v.z - mean) * rstd + b4.z;
    float o3 = w4.w * (v.w - mean) * rstd + b4.w;
    __nv_bfloat16 h0, l0, h1, l1, h2, l2, h3, l3;
    split2(o0, h0, l0); split2(o1, h1, l1); split2(o2, h2, l2); split2(o3, h3, l3);
    size_t base = (size_t)row * Dn + tid * 4;
    ((__nv_bfloat162*)(yh + base))[0] = __nv_bfloat162(h0, h1);
    ((__nv_bfloat162*)(yh + base))[1] = __nv_bfloat162(h2, h3);
    ((__nv_bfloat162*)(yl + base))[0] = __nv_bfloat162(l0, l1);
    ((__nv_bfloat162*)(yl + base))[1] = __nv_bfloat162(l2, l3);
}

// ============== softmax: fp32 scores -> split-bf16 probs ========================
__global__ __launch_bounds__(256) void softmax_split(
    const float* __restrict__ sc, float scale, int causal,
    const float* __restrict__ addmask,
    __nv_bfloat16* __restrict__ ph, __nv_bfloat16* __restrict__ pl)
{
    const int row = blockIdx.x;
    const int s = row & (Sn - 1);
    const int b = row >> 14;
    const float* p = sc + (size_t)row * Tn;
    const int tid = threadIdx.x;

    float vals[4];
    float mx = -1e30f;
    #pragma unroll
    for (int i = 0; i < 4; i++) {
        int c = tid + i * 256;
        float v = p[c] * scale;
        if (causal) { if (c > s) v = -10000.0f; }
        else if (addmask) v += addmask[(size_t)b * Tn + c];
        vals[i] = v;
        mx = fmaxf(mx, v);
    }
    __shared__ float sm[18];
    #pragma unroll
    for (int off = 16; off > 0; off >>= 1) mx = fmaxf(mx, __shfl_xor_sync(~0u, mx, off));
    if ((tid & 31) == 0) sm[tid >> 5] = mx;
    __syncthreads();
    if (tid < 32) {
        float a = (tid < 8) ? sm[tid] : -1e30f;
        #pragma unroll
        for (int off = 4; off > 0; off >>= 1) a = fmaxf(a, __shfl_xor_sync(~0u, a, off));
        if (tid == 0) sm[16] = a;
    }
    __syncthreads();
    const float m = sm[16];

    float sum = 0.f;
    #pragma unroll
    for (int i = 0; i < 4; i++) { vals[i] = expf(vals[i] - m); sum += vals[i]; }
    #pragma unroll
    for (int off = 16; off > 0; off >>= 1) sum += __shfl_xor_sync(~0u, sum, off);
    if ((tid & 31) == 0) sm[tid >> 5] = sum;
    __syncthreads();
    if (tid < 32) {
        float a = (tid < 8) ? sm[tid] : 0.f;
        #pragma unroll
        for (int off = 4; off > 0; off >>= 1) a += __shfl_xor_sync(~0u, a, off);
        if (tid == 0) sm[17] = a;
    }
    __syncthreads();
    const float inv = 1.0f / sm[17];
    #pragma unroll
    for (int i = 0; i < 4; i++) {
        int c = tid + i * 256;
        __nv_bfloat16 hh, ll;
        split2(vals[i] * inv, hh, ll);
        ph[(size_t)row * Tn + c] = hh;
        pl[(size_t)row * Tn + c] = ll;
    }
}

// -------------------------------- launcher --------------------------------------
extern "C" void kernel_launch(void* const* d_in, const int* in_sizes, int n_in,
                              void* d_out, int out_size)
{
    const float* hid      = (const float*)d_in[0];
    const float* enc      = (const float*)d_in[1];
    const float* enc_mask = (const float*)d_in[2];
    const float *ln1_w = (const float*)d_in[4],  *ln1_b = (const float*)d_in[5];
    const float *qkv_w = (const float*)d_in[6],  *qkv_b = (const float*)d_in[7];
    const float *ao_w  = (const float*)d_in[8],  *ao_b  = (const float*)d_in[9];
    const float *ln2_w = (const float*)d_in[10], *ln2_b = (const float*)d_in[11];
    const float *q_w   = (const float*)d_in[12], *q_b   = (const float*)d_in[13];
    const float *kv_w  = (const float*)d_in[14], *kv_b  = (const float*)d_in[15];
    const float *co_w  = (const float*)d_in[16], *co_b  = (const float*)d_in[17];
    const float *ln3_w = (const float*)d_in[18], *ln3_b = (const float*)d_in[19];
    const float *fi_w  = (const float*)d_in[20], *fi_b  = (const float*)d_in[21];
    const float *fo_w  = (const float*)d_in[22], *fo_b  = (const float*)d_in[23];
    float* out = (float*)d_out;

    float *sc, *hb;
    __nv_bfloat16 *qkvh, *qkvl, *qh, *ql, *kvh, *kvl, *ph, *pl, *vth, *vtl;
    __nv_bfloat16 *lnh, *lnl, *ctxh, *ctxl, *ench, *encl, *ffnh, *ffnl, *wth, *wtl;
    cudaGetSymbolAddress((void**)&sc,   g_sc);
    cudaGetSymbolAddress((void**)&hb,   g_h);
    cudaGetSymbolAddress((void**)&qkvh, g_qkvh);
    cudaGetSymbolAddress((void**)&qkvl, g_qkvl);
    cudaGetSymbolAddress((void**)&qh,   g_qh);
    cudaGetSymbolAddress((void**)&ql,   g_ql);
    cudaGetSymbolAddress((void**)&kvh,  g_kvh);
    cudaGetSymbolAddress((void**)&kvl,  g_kvl);
    cudaGetSymbolAddress((void**)&ph,   g_ph);
    cudaGetSymbolAddress((void**)&pl,   g_pl);
    cudaGetSymbolAddress((void**)&vth,  g_vth);
    cudaGetSymbolAddress((void**)&vtl,  g_vtl);
    cudaGetSymbolAddress((void**)&lnh,  g_lnh);
    cudaGetSymbolAddress((void**)&lnl,  g_lnl);
    cudaGetSymbolAddress((void**)&ctxh, g_ctxh);
    cudaGetSymbolAddress((void**)&ctxl, g_ctxl);
    cudaGetSymbolAddress((void**)&ench, g_ench);
    cudaGetSymbolAddress((void**)&encl, g_encl);
    cudaGetSymbolAddress((void**)&ffnh, g_ffnh);
    cudaGetSymbolAddress((void**)&ffnl, g_ffnl);
    cudaGetSymbolAddress((void**)&wth,  g_wth);
    cudaGetSymbolAddress((void**)&wtl,  g_wtl);

    static bool attr_done = false;
    if (!attr_done) {
        cudaFuncSetAttribute(tgemm<128>, cudaFuncAttributeMaxDynamicSharedMemorySize, 65536);
        cudaFuncSetAttribute(tgemm<64>,  cudaFuncAttributeMaxDynamicSharedMemorySize, 49152);
        attr_done = true;
    }
    const int SM128 = 65536, SM64 = 49152;
    const int M = Mrows;  // 4096
    const size_t ZST = (size_t)Sn * Tn;

    // ---- weight conversion (transpose + split) ----
    wsplitT<<<dim3(3072 / 32, 1024 / 32), 256>>>(qkv_w, wth + OW_QKV, wtl + OW_QKV, 1024, 3072);
    wsplitT<<<dim3(1024 / 32, 1024 / 32), 256>>>(ao_w,  wth + OW_AO,  wtl + OW_AO,  1024, 1024);
    wsplitT<<<dim3(1024 / 32, 1024 / 32), 256>>>(q_w,   wth + OW_Q,   wtl + OW_Q,   1024, 1024);
    wsplitT<<<dim3(2048 / 32, 1024 / 32), 256>>>(kv_w,  wth + OW_KV,  wtl + OW_KV,  1024, 2048);
    wsplitT<<<dim3(1024 / 32, 1024 / 32), 256>>>(co_w,  wth + OW_CO,  wtl + OW_CO,  1024, 1024);
    wsplitT<<<dim3(4096 / 32, 1024 / 32), 256>>>(fi_w,  wth + OW_FI,  wtl + OW_FI,  1024, 4096);
    wsplitT<<<dim3(1024 / 32, 4096 / 32), 256>>>(fo_w,  wth + OW_FO,  wtl + OW_FO,  4096, 1024);
    esplit<<<(M * Dn / 4) / 256, 256>>>(enc, ench, encl);

    // ==== self-attention block ====
    ln_split<<<M, 256>>>(hid, ln1_w, ln1_b, lnh, lnl);
    tgemm<128><<<dim3(3072 / 128, M / 128, 1), 256, SM128>>>(
        lnh, lnl, 1024, 0, 0, wth + OW_QKV, wtl + OW_QKV, 1024, 0, 0,
        qkv_b, nullptr, nullptr, qkvh, qkvl, 3072, 0, 0, 1024, 0);
    vtransT<<<dim3(32, 2, 64), 256>>>(qkvh, qkvl, 3072, 2048, vth, vtl);
    tgemm<128><<<dim3(8, 8, 64), 256, SM128>>>(                       // scores = Q.K^T
        qkvh, qkvl, 3072, (size_t)Sn * 3072, 64,
        qkvh + 1024, qkvl + 1024, 3072, (size_t)Sn * 3072, 64,
        nullptr, nullptr, sc, nullptr, nullptr, 1024, 16 * ZST, ZST, 64, 0);
    softmax_split<<<64 * Sn, 256>>>(sc, SCALE, 1, nullptr, ph, pl);
    tgemm<64><<<dim3(1, 8, 64), 256, SM64>>>(                          // ctx = P.V
        ph, pl, 1024, 16 * ZST, ZST,
        vth, vtl, 1024, (size_t)16 * 64 * 1024, (size_t)64 * 1024,
        nullptr, nullptr, nullptr, ctxh, ctxl, 1024, (size_t)Sn * Dn, 64, 1024, 0);
    tgemm<128><<<dim3(8, M / 128, 1), 256, SM128>>>(
        ctxh, ctxl, 1024, 0, 0, wth + OW_AO, wtl + OW_AO, 1024, 0, 0,
        ao_b, hid, hb, nullptr, nullptr, 1024, 0, 0, 1024, 0);

    // ==== cross-attention block ====
    ln_split<<<M, 256>>>(hb, ln2_w, ln2_b, lnh, lnl);
    tgemm<128><<<dim3(8, M / 128, 1), 256, SM128>>>(
        lnh, lnl, 1024, 0, 0, wth + OW_Q, wtl + OW_Q, 1024, 0, 0,
        q_b, nullptr, nullptr, qh, ql, 1024, 0, 0, 1024, 0);
    tgemm<128><<<dim3(16, M / 128, 1), 256, SM128>>>(
        ench, encl, 1024, 0, 0, wth + OW_KV, wtl + OW_KV, 1024, 0, 0,
        kv_b, nullptr, nullptr, kvh, kvl, 2048, 0, 0, 1024, 0);
    vtransT<<<dim3(32, 2, 64), 256>>>(kvh, kvl, 2048, 1024, vth, vtl);
    tgemm<128><<<dim3(8, 8, 64), 256, SM128>>>(
        qh, ql, 1024, (size_t)Sn * 1024, 64,
        kvh, kvl, 2048, (size_t)Sn * 2048, 64,
        nullptr, nullptr, sc, nullptr, nullptr, 1024, 16 * ZST, ZST, 64, 0);
    softmax_split<<<64 * Sn, 256>>>(sc, SCALE, 0, enc_mask, ph, pl);
    tgemm<64><<<dim3(1, 8, 64), 256, SM64>>>(
        ph, pl, 1024, 16 * ZST, ZST,
        vth, vtl, 1024, (size_t)16 * 64 * 1024, (size_t)64 * 1024,
        nullptr, nullptr, nullptr, ctxh, ctxl, 1024, (size_t)Sn * Dn, 64, 1024, 0);
    tgemm<128><<<dim3(8, M / 128, 1), 256, SM128>>>(
        ctxh, ctxl, 1024, 0, 0, wth + OW_CO, wtl + OW_CO, 1024, 0, 0,
        co_b, hb, hb, nullptr, nullptr, 1024, 0, 0, 1024, 0);

    // ==== FFN block ====
    ln_split<<<M, 256>>>(hb, ln3_w, ln3_b, lnh, lnl);
    tgemm<128><<<dim3(32, M / 128, 1), 256, SM128>>>(
        lnh, lnl, 1024, 0, 0, wth + OW_FI, wtl + OW_FI, 1024, 0, 0,
        fi_b, nullptr, nullptr, ffnh, ffnl, 4096, 0, 0, 1024, 1);
    tgemm<128><<<dim3(8, M / 128, 1), 256, SM128>>>(
        ffnh, ffnl, 4096, 0, 0, wth + OW_FO, wtl + OW_FO, 4096, 0, 0,
        fo_b, hb, out, nullptr, nullptr, 1024, 0, 0, 4096, 0);
}

// round 8
// speedup vs baseline: 2.4152x; 1.0205x over previous
#include <cuda_runtime.h>
#include <cuda_bf16.h>
#include <math.h>
#include <stdint.h>

// Problem constants
constexpr int Bn = 4, Sn = 1024, Tn = 1024, Dn = 1024, Fn = 4096;
constexpr int Mrows = Bn * Sn;           // 4096
constexpr float SCALE = 0.125f;          // 1/sqrt(64)

// ---------------- scratch (static device globals: allocation-free) -------------
__device__ __align__(256) float g_sc [(size_t)64 * Sn * Tn];   // 256 MB scores
__device__ __align__(256) float g_h  [Mrows * Dn];             // fp32 hidden

__device__ __align__(256) __nv_bfloat16 g_qkvh[Mrows * 3 * Dn];
__device__ __align__(256) __nv_bfloat16 g_qkvl[Mrows * 3 * Dn];
__device__ __align__(256) __nv_bfloat16 g_qh  [Mrows * Dn];
__device__ __align__(256) __nv_bfloat16 g_ql  [Mrows * Dn];
__device__ __align__(256) __nv_bfloat16 g_kvh [Mrows * 2 * Dn];
__device__ __align__(256) __nv_bfloat16 g_kvl [Mrows * 2 * Dn];
__device__ __align__(256) __nv_bfloat16 g_ph  [(size_t)64 * Sn * Tn];
__device__ __align__(256) __nv_bfloat16 g_pl  [(size_t)64 * Sn * Tn];
__device__ __align__(256) __nv_bfloat16 g_vth [64 * 64 * 1024];
__device__ __align__(256) __nv_bfloat16 g_vtl [64 * 64 * 1024];

__device__ __align__(256) __nv_bfloat16 g_lnh [Mrows * Dn];
__device__ __align__(256) __nv_bfloat16 g_lnl [Mrows * Dn];
__device__ __align__(256) __nv_bfloat16 g_ctxh[Mrows * Dn];
__device__ __align__(256) __nv_bfloat16 g_ctxl[Mrows * Dn];
__device__ __align__(256) __nv_bfloat16 g_ench[Mrows * Dn];
__device__ __align__(256) __nv_bfloat16 g_encl[Mrows * Dn];
__device__ __align__(256) __nv_bfloat16 g_ffnh[(size_t)Mrows * Fn];
__device__ __align__(256) __nv_bfloat16 g_ffnl[(size_t)Mrows * Fn];
__device__ __align__(256) __nv_bfloat16 g_wth[16 * 1024 * 1024];
__device__ __align__(256) __nv_bfloat16 g_wtl[16 * 1024 * 1024];
constexpr size_t OW_QKV = 0;
constexpr size_t OW_AO  = OW_QKV + 3u*1024*1024;
constexpr size_t OW_Q   = OW_AO  + 1u*1024*1024;
constexpr size_t OW_KV  = OW_Q   + 1u*1024*1024;
constexpr size_t OW_CO  = OW_KV  + 2u*1024*1024;
constexpr size_t OW_FI  = OW_CO  + 1u*1024*1024;
constexpr size_t OW_FO  = OW_FI  + 4u*1024*1024;

// ================= helpers ======================================================
__device__ __forceinline__ uint32_t s2u(const void* p) {
    uint32_t a;
    asm("{ .reg .u64 t; cvta.to.shared.u64 t, %1; cvt.u32.u64 %0, t; }" : "=r"(a) : "l"(p));
    return a;
}
__device__ __forceinline__ void ldsm4(uint32_t& r0, uint32_t& r1, uint32_t& r2, uint32_t& r3,
                                      uint32_t a) {
    asm volatile("ldmatrix.sync.aligned.m8n8.x4.shared.b16 {%0,%1,%2,%3}, [%4];"
        : "=r"(r0), "=r"(r1), "=r"(r2), "=r"(r3) : "r"(a));
}
__device__ __forceinline__ void mma16816(float* c, const uint32_t* a, uint32_t b0, uint32_t b1) {
    asm volatile(
        "mma.sync.aligned.m16n8k16.row.col.f32.bf16.bf16.f32 "
        "{%0,%1,%2,%3}, {%4,%5,%6,%7}, {%8,%9}, {%0,%1,%2,%3};"
        : "+f"(c[0]), "+f"(c[1]), "+f"(c[2]), "+f"(c[3])
        : "r"(a[0]), "r"(a[1]), "r"(a[2]), "r"(a[3]), "r"(b0), "r"(b1));
}
__device__ __forceinline__ void cpa16(uint32_t dst, const void* src) {
    asm volatile("cp.async.ca.shared.global [%0], [%1], 16;" :: "r"(dst), "l"(src));
}
__device__ __forceinline__ void split2(float x, __nv_bfloat16& h, __nv_bfloat16& l) {
    h = __float2bfloat16(x);
    l = __float2bfloat16(x - __bfloat162float(h));
}

// ================= tensor-core split-bf16 GEMM (mma.sync HMMA) ==================
// Batched: z = blockIdx.z, b=z>>4, h=z&15; operand offset = b*sXb + h*sXh.
// A split [*,K] (row stride lda), B split [N,K] (row stride ldb), both K-major.
// C = A@B^T (+bias)(+GELU)(+res); outputs fp32 (Cf) and/or split bf16 (Ch/Cl).
// trimask: skip tiles fully above the causal diagonal (n0 > m0+127).
// kcausal: limit K to the causal frontier of this 128-row block.
template<int BN>
__global__ __launch_bounds__(256)
void tgemm(const __nv_bfloat16* __restrict__ Ah_, const __nv_bfloat16* __restrict__ Al_,
           int lda, size_t sAb, size_t sAh,
           const __nv_bfloat16* __restrict__ Bh_, const __nv_bfloat16* __restrict__ Bl_,
           int ldb, size_t sBb, size_t sBh,
           const float* __restrict__ bias, const float* __restrict__ res,
           float* __restrict__ Cf, __nv_bfloat16* __restrict__ Ch, __nv_bfloat16* __restrict__ Cl,
           int ldc, size_t sCb, size_t sCh,
           int K, int gelu, int trimask, int kcausal)
{
    constexpr int STAGE = 16384 + BN * 128;      // bytes per pipeline stage
    constexpr int LP    = (128 + BN) * 8 / 256;  // 16B loads per thread per stage
    constexpr int NTC   = BN / 16;               // 8-col n-tiles per warp
    constexpr int NJ    = BN / 32;               // ldsm-b iterations

    extern __shared__ __align__(1024) char smraw[];
    const uint32_t sbase = s2u(smraw);
    const int tid = threadIdx.x, lane = tid & 31, wid = tid >> 5;
    const int z = blockIdx.z, zb = z >> 4, zh = z & 15;
    const int m0 = blockIdx.y * 128, n0 = blockIdx.x * BN;
    const int wm = wid & 3, wn = wid >> 2;

    if (trimask && n0 > m0 + 127) return;        // fully-masked causal tile
    const int Ke = kcausal ? min(K, ((m0 >> 8) + 1) << 8) : K;

    const __nv_bfloat16* Ahp = Ah_ + zb * sAb + zh * sAh + (size_t)m0 * lda;
    const __nv_bfloat16* Alp = Al_ + zb * sAb + zh * sAh + (size_t)m0 * lda;
    const __nv_bfloat16* Bhp = Bh_ + zb * sBb + zh * sBh + (size_t)n0 * ldb;
    const __nv_bfloat16* Blp = Bl_ + zb * sBb + zh * sBh + (size_t)n0 * ldb;
    const size_t coff = zb * sCb + zh * sCh;

    float acc[2][NTC][4] = {};

    auto stage = [&](int st, int k0) {
        uint32_t dst0 = sbase + st * STAGE;
        #pragma unroll
        for (int p = 0; p < LP; p++) {
            int idx = tid + p * 256;
            int isB = idx >= 1024;
            int s = isB ? idx - 1024 : idx;
            int r = s >> 3, q = s & 7;
            const __nv_bfloat16* src = isB
                ? ((q < 4 ? Bhp : Blp) + (size_t)r * ldb + k0 + (q & 3) * 8)
                : ((q < 4 ? Ahp : Alp) + (size_t)r * lda + k0 + (q & 3) * 8);
            uint32_t dst = dst0 + isB * 16384 + r * 128 + ((q * 16) ^ ((r & 7) * 16));
            cpa16(dst, src);
        }
        asm volatile("cp.async.commit_group;" ::: "memory");
    };

    auto compute = [&](int st) {
        uint32_t sA = sbase + st * STAGE, sB = sA + 16384;
        #pragma unroll
        for (int ks = 0; ks < 2; ks++) {
            uint32_t ah[2][4], al[2][4];
            #pragma unroll
            for (int mt = 0; mt < 2; mt++) {
                int row = wm * 32 + mt * 16 + (lane & 15);
                int kb = ks * 32 + (lane >> 4) * 16;
                uint32_t rb = sA + row * 128;
                uint32_t xr = (row & 7) * 16;
                ldsm4(ah[mt][0], ah[mt][1], ah[mt][2], ah[mt][3], rb + (kb ^ xr));
                ldsm4(al[mt][0], al[mt][1], al[mt][2], al[mt][3], rb + ((kb + 64) ^ xr));
            }
            #pragma unroll
            for (int j = 0; j < NJ; j++) {
                int g = lane >> 3;
                int row = wn * (BN / 2) + (j * 2 + (g >> 1)) * 8 + (lane & 7);
                int kb = ks * 32 + (g & 1) * 16;
                uint32_t rb = sB + row * 128;
                uint32_t xr = (row & 7) * 16;
                uint32_t bh[4], bl[4];
                ldsm4(bh[0], bh[1], bh[2], bh[3], rb + (kb ^ xr));
                ldsm4(bl[0], bl[1], bl[2], bl[3], rb + ((kb + 64) ^ xr));
                #pragma unroll
                for (int mt = 0; mt < 2; mt++) {
                    #pragma unroll
                    for (int t = 0; t < 2; t++) {
                        float* c = acc[mt][j * 2 + t];
                        mma16816(c, ah[mt], bh[2 * t], bh[2 * t + 1]);
                        mma16816(c, ah[mt], bl[2 * t], bl[2 * t + 1]);
                        mma16816(c, al[mt], bh[2 * t], bh[2 * t + 1]);
                    }
                }
            }
        }
    };

    const int NC = Ke >> 5;
    stage(0, 0);
    for (int c = 0; c < NC; c++) {
        asm volatile("cp.async.wait_group 0;" ::: "memory");
        __syncthreads();
        if (c + 1 < NC) stage((c + 1) & 1, (c + 1) * 32);
        compute(c & 1);
    }

    // ---- epilogue ----
    const int r_in = lane >> 2, c_in = (lane & 3) * 2;
    #pragma unroll
    for (int mt = 0; mt < 2; mt++) {
        #pragma unroll
        for (int rr = 0; rr < 2; rr++) {
            int row = m0 + wm * 32 + mt * 16 + rr * 8 + r_in;
            #pragma unroll
            for (int nt = 0; nt < NTC; nt++) {
                int col = n0 + wn * (BN / 2) + nt * 8 + c_in;
                float v0 = acc[mt][nt][rr * 2 + 0];
                float v1 = acc[mt][nt][rr * 2 + 1];
                if (bias) { v0 += bias[col]; v1 += bias[col + 1]; }
                if (gelu) {
                    v0 = 0.5f * v0 * (1.0f + erff(v0 * 0.7071067811865476f));
                    v1 = 0.5f * v1 * (1.0f + erff(v1 * 0.7071067811865476f));
                }
                size_t off = coff + (size_t)row * ldc + col;
                if (res) {
                    float2 rr2 = *(const float2*)(res + off);
                    v0 += rr2.x; v1 += rr2.y;
                }
                if (Cf) *(float2*)(Cf + off) = make_float2(v0, v1);
                if (Ch) {
                    __nv_bfloat16 h0, l0, h1, l1;
                    split2(v0, h0, l0); split2(v1, h1, l1);
                    *(__nv_bfloat162*)(Ch + off) = __nv_bfloat162(h0, h1);
                    *(__nv_bfloat162*)(Cl + off) = __nv_bfloat162(l0, l1);
                }
            }
        }
    }
}

// ============== V transpose: vt[z][d][t] = v[(b*S+t)*ld + off + h*64 + d] =======
__global__ __launch_bounds__(256) void vtransT(
    const __nv_bfloat16* __restrict__ inh, const __nv_bfloat16* __restrict__ inl,
    int ld, int off, __nv_bfloat16* __restrict__ oth, __nv_bfloat16* __restrict__ otl)
{
    __shared__ __nv_bfloat16 th[32][33], tl[32][33];
    const int z = blockIdx.z, b = z >> 4, h = z & 15;
    const int t0 = blockIdx.x * 32, d0 = blockIdx.y * 32;
    const int tx = threadIdx.x & 31, ty = threadIdx.x >> 5;
    const __nv_bfloat16* sh = inh + (size_t)b * Sn * ld + off + h * 64 + d0;
    const __nv_bfloat16* sl = inl + (size_t)b * Sn * ld + off + h * 64 + d0;
    #pragma unroll
    for (int i = 0; i < 4; i++) {
        int t = t0 + ty + i * 8;
        th[ty + i * 8][tx] = sh[(size_t)t * ld + tx];
        tl[ty + i * 8][tx] = sl[(size_t)t * ld + tx];
    }
    __syncthreads();
    size_t obase = (size_t)z * 64 * 1024;
    #pragma unroll
    for (int i = 0; i < 4; i++) {
        int d = d0 + ty + i * 8;
        oth[obase + (size_t)d * 1024 + t0 + tx] = th[tx][ty + i * 8];
        otl[obase + (size_t)d * 1024 + t0 + tx] = tl[tx][ty + i * 8];
    }
}

// ============== weight transpose + split: W[K,N] -> Wh/Wl[N,K] bf16 =============
__global__ __launch_bounds__(256) void wsplitT(
    const float* __restrict__ W, __nv_bfloat16* __restrict__ oh,
    __nv_bfloat16* __restrict__ ol, int K, int N)
{
    __shared__ float t[32][33];
    int tx = threadIdx.x & 31, ty = threadIdx.x >> 5;
    int n0 = blockIdx.x * 32, k0 = blockIdx.y * 32;
    #pragma unroll
    for (int i = 0; i < 4; i++)
        t[ty + i * 8][tx] = W[(size_t)(k0 + ty + i * 8) * N + n0 + tx];
    __syncthreads();
    #pragma unroll
    for (int i = 0; i < 4; i++) {
        float v = t[tx][ty + i * 8];
        __nv_bfloat16 h, l;
        split2(v, h, l);
        size_t o = (size_t)(n0 + ty + i * 8) * K + k0 + tx;
        oh[o] = h; ol[o] = l;
    }
}

// ============== elementwise split (enc hidden states) ===========================
__global__ __launch_bounds__(256) void esplit(
    const float* __restrict__ x, __nv_bfloat16* __restrict__ oh,
    __nv_bfloat16* __restrict__ ol)
{
    int i = blockIdx.x * 256 + threadIdx.x;
    float4 v = ((const float4*)x)[i];
    __nv_bfloat16 h0, l0, h1, l1, h2, l2, h3, l3;
    split2(v.x, h0, l0); split2(v.y, h1, l1); split2(v.z, h2, l2); split2(v.w, h3, l3);
    ((__nv_bfloat162*)oh)[2 * i]     = __nv_bfloat162(h0, h1);
    ((__nv_bfloat162*)oh)[2 * i + 1] = __nv_bfloat162(h2, h3);
    ((__nv_bfloat162*)ol)[2 * i]     = __nv_bfloat162(l0, l1);
    ((__nv_bfloat162*)ol)[2 * i + 1] = __nv_bfloat162(l2, l3);
}

// ============== LayerNorm -> split bf16 =========================================
__global__ __launch_bounds__(256) void ln_split(
    const float* __restrict__ x, const float* __restrict__ w,
    const float* __restrict__ bb, __nv_bfloat16* __restrict__ yh,
    __nv_bfloat16* __restrict__ yl)
{
    const int row = blockIdx.x, tid = threadIdx.x;
    float4 v = ((const float4*)(x + (size_t)row * Dn))[tid];
    float s  = v.x + v.y + v.z + v.w;
    float sq = v.x * v.x + v.y * v.y + v.z * v.z + v.w * v.w;

    __shared__ float sm[18];
    #pragma unroll
    for (int off = 16; off > 0; off >>= 1) {
        s  += __shfl_xor_sync(~0u, s,  off);
        sq += __shfl_xor_sync(~0u, sq, off);
    }
    if ((tid & 31) == 0) { sm[tid >> 5] = s; sm[(tid >> 5) + 8] = sq; }
    __syncthreads();
    if (tid < 32) {
        float a  = (tid < 8) ? sm[tid]     : 0.f;
        float aq = (tid < 8) ? sm[tid + 8] : 0.f;
        #pragma unroll
        for (int off = 4; off > 0; off >>= 1) {
            a  += __shfl_xor_sync(~0u, a,  off);
            aq += __shfl_xor_sync(~0u, aq, off);
        }
        if (tid == 0) { sm[16] = a; sm[17] = aq; }
    }
    __syncthreads();
    const float mean = sm[16] * (1.0f / Dn);
    const float var  = sm[17] * (1.0f / Dn) - mean * mean;
    const float rstd = rsqrtf(var + 1e-12f);

    float4 w4 = ((const float4*)w)[tid];
    float4 b4 = ((const float4*)bb)[tid];
    float o0 = w4.x * (v.x - mean) * rstd + b4.x;
    float o1 = w4.y * (v.y - mean) * rstd + b4.y;
    float o2 = w4.z * (v.z - mean) * rstd + b4.z;
    float o3 = w4.w * (v.w - mean) * rstd + b4.w;
    __nv_bfloat16 h0, l0, h1, l1, h2, l2, h3, l3;
    split2(o0, h0, l0); split2(o1, h1, l1); split2(o2, h2, l2); split2(o3, h3, l3);
    size_t base = (size_t)row * Dn + tid * 4;
    ((__nv_bfloat162*)(yh + base))[0] = __nv_bfloat162(h0, h1);
    ((__nv_bfloat162*)(yh + base))[1] = __nv_bfloat162(h2, h3);
    ((__nv_bfloat162*)(yl + base))[0] = __nv_bfloat162(l0, l1);
    ((__nv_bfloat162*)(yl + base))[1] = __nv_bfloat162(l2, l3);
}

// ============== softmax: fp32 scores -> split-bf16 probs ========================
// causal: only process cols < cend = round256(s+1); masked cols get prob 0
// (matches reference: score -10000 -> exp underflows to exactly 0).
__global__ __launch_bounds__(256) void softmax_split(
    const float* __restrict__ sc, float scale, int causal,
    const float* __restrict__ addmask,
    __nv_bfloat16* __restrict__ ph, __nv_bfloat16* __restrict__ pl)
{
    const int row = blockIdx.x;
    const int s = row & (Sn - 1);
    const int b = row >> 14;
    const float* p = sc + (size_t)row * Tn;
    const int tid = threadIdx.x;

    const int ni = causal ? (s >> 8) + 1 : 4;   // 256-col chunks to process

    float vals[4];
    float mx = -1e30f;
    for (int i = 0; i < ni; i++) {
        int c = tid + i * 256;
        float v;
        if (causal && c > s) v = -10000.0f;
        else {
            v = p[c] * scale;
            if (!causal && addmask) v += addmask[(size_t)b * Tn + c];
        }
        vals[i] = v;
        mx = fmaxf(mx, v);
    }
    __shared__ float sm[18];
    #pragma unroll
    for (int off = 16; off > 0; off >>= 1) mx = fmaxf(mx, __shfl_xor_sync(~0u, mx, off));
    if ((tid & 31) == 0) sm[tid >> 5] = mx;
    __syncthreads();
    if (tid < 32) {
        float a = (tid < 8) ? sm[tid] : -1e30f;
        #pragma unroll
        for (int off = 4; off > 0; off >>= 1) a = fmaxf(a, __shfl_xor_sync(~0u, a, off));
        if (tid == 0) sm[16] = a;
    }
    __syncthreads();
    const float m = sm[16];

    float sum = 0.f;
    for (int i = 0; i < ni; i++) { vals[i] = expf(vals[i] - m); sum += vals[i]; }
    #pragma unroll
    for (int off = 16; off > 0; off >>= 1) sum += __shfl_xor_sync(~0u, sum, off);
    if ((tid & 31) == 0) sm[tid >> 5] = sum;
    __syncthreads();
    if (tid < 32) {
        float a = (tid < 8) ? sm[tid] : 0.f;
        #pragma unroll
        for (int off = 4; off > 0; off >>= 1) a += __shfl_xor_sync(~0u, a, off);
        if (tid == 0) sm[17] = a;
    }
    __syncthreads();
    const float inv = 1.0f / sm[17];
    for (int i = 0; i < ni; i++) {
        int c = tid + i * 256;
        __nv_bfloat16 hh, ll;
        split2(vals[i] * inv, hh, ll);
        ph[(size_t)row * Tn + c] = hh;
        pl[(size_t)row * Tn + c] = ll;
    }
}

// -------------------------------- launcher --------------------------------------
extern "C" void kernel_launch(void* const* d_in, const int* in_sizes, int n_in,
                              void* d_out, int out_size)
{
    const float* hid      = (const float*)d_in[0];
    const float* enc      = (const float*)d_in[1];
    const float* enc_mask = (const float*)d_in[2];
    const float *ln1_w = (const float*)d_in[4],  *ln1_b = (const float*)d_in[5];
    const float *qkv_w = (const float*)d_in[6],  *qkv_b = (const float*)d_in[7];
    const float *ao_w  = (const float*)d_in[8],  *ao_b  = (const float*)d_in[9];
    const float *ln2_w = (const float*)d_in[10], *ln2_b = (const float*)d_in[11];
    const float *q_w   = (const float*)d_in[12], *q_b   = (const float*)d_in[13];
    const float *kv_w  = (const float*)d_in[14], *kv_b  = (const float*)d_in[15];
    const float *co_w  = (const float*)d_in[16], *co_b  = (const float*)d_in[17];
    const float *ln3_w = (const float*)d_in[18], *ln3_b = (const float*)d_in[19];
    const float *fi_w  = (const float*)d_in[20], *fi_b  = (const float*)d_in[21];
    const float *fo_w  = (const float*)d_in[22], *fo_b  = (const float*)d_in[23];
    float* out = (float*)d_out;

    float *sc, *hb;
    __nv_bfloat16 *qkvh, *qkvl, *qh, *ql, *kvh, *kvl, *ph, *pl, *vth, *vtl;
    __nv_bfloat16 *lnh, *lnl, *ctxh, *ctxl, *ench, *encl, *ffnh, *ffnl, *wth, *wtl;
    cudaGetSymbolAddress((void**)&sc,   g_sc);
    cudaGetSymbolAddress((void**)&hb,   g_h);
    cudaGetSymbolAddress((void**)&qkvh, g_qkvh);
    cudaGetSymbolAddress((void**)&qkvl, g_qkvl);
    cudaGetSymbolAddress((void**)&qh,   g_qh);
    cudaGetSymbolAddress((void**)&ql,   g_ql);
    cudaGetSymbolAddress((void**)&kvh,  g_kvh);
    cudaGetSymbolAddress((void**)&kvl,  g_kvl);
    cudaGetSymbolAddress((void**)&ph,   g_ph);
    cudaGetSymbolAddress((void**)&pl,   g_pl);
    cudaGetSymbolAddress((void**)&vth,  g_vth);
    cudaGetSymbolAddress((void**)&vtl,  g_vtl);
    cudaGetSymbolAddress((void**)&lnh,  g_lnh);
    cudaGetSymbolAddress((void**)&lnl,  g_lnl);
    cudaGetSymbolAddress((void**)&ctxh, g_ctxh);
    cudaGetSymbolAddress((void**)&ctxl, g_ctxl);
    cudaGetSymbolAddress((void**)&ench, g_ench);
    cudaGetSymbolAddress((void**)&encl, g_encl);
    cudaGetSymbolAddress((void**)&ffnh, g_ffnh);
    cudaGetSymbolAddress((void**)&ffnl, g_ffnl);
    cudaGetSymbolAddress((void**)&wth,  g_wth);
    cudaGetSymbolAddress((void**)&wtl,  g_wtl);

    static bool attr_done = false;
    if (!attr_done) {
        cudaFuncSetAttribute(tgemm<256>, cudaFuncAttributeMaxDynamicSharedMemorySize, 98304);
        cudaFuncSetAttribute(tgemm<128>, cudaFuncAttributeMaxDynamicSharedMemorySize, 65536);
        cudaFuncSetAttribute(tgemm<64>,  cudaFuncAttributeMaxDynamicSharedMemorySize, 49152);
        attr_done = true;
    }
    const int SM256 = 98304, SM128 = 65536, SM64 = 49152;
    const int M = Mrows;  // 4096
    const size_t ZST = (size_t)Sn * Tn;

    // ---- weight conversion (transpose + split) ----
    wsplitT<<<dim3(3072 / 32, 1024 / 32), 256>>>(qkv_w, wth + OW_QKV, wtl + OW_QKV, 1024, 3072);
    wsplitT<<<dim3(1024 / 32, 1024 / 32), 256>>>(ao_w,  wth + OW_AO,  wtl + OW_AO,  1024, 1024);
    wsplitT<<<dim3(1024 / 32, 1024 / 32), 256>>>(q_w,   wth + OW_Q,   wtl + OW_Q,   1024, 1024);
    wsplitT<<<dim3(2048 / 32, 1024 / 32), 256>>>(kv_w,  wth + OW_KV,  wtl + OW_KV,  1024, 2048);
    wsplitT<<<dim3(1024 / 32, 1024 / 32), 256>>>(co_w,  wth + OW_CO,  wtl + OW_CO,  1024, 1024);
    wsplitT<<<dim3(4096 / 32, 1024 / 32), 256>>>(fi_w,  wth + OW_FI,  wtl + OW_FI,  1024, 4096);
    wsplitT<<<dim3(1024 / 32, 4096 / 32), 256>>>(fo_w,  wth + OW_FO,  wtl + OW_FO,  4096, 1024);
    esplit<<<(M * Dn / 4) / 256, 256>>>(enc, ench, encl);

    // ==== self-attention block ====
    ln_split<<<M, 256>>>(hid, ln1_w, ln1_b, lnh, lnl);
    tgemm<256><<<dim3(12, M / 128, 1), 256, SM256>>>(
        lnh, lnl, 1024, 0, 0, wth + OW_QKV, wtl + OW_QKV, 1024, 0, 0,
        qkv_b, nullptr, nullptr, qkvh, qkvl, 3072, 0, 0, 1024, 0, 0, 0);
    vtransT<<<dim3(32, 2, 64), 256>>>(qkvh, qkvl, 3072, 2048, vth, vtl);
    tgemm<128><<<dim3(8, 8, 64), 256, SM128>>>(                       // scores = Q.K^T
        qkvh, qkvl, 3072, (size_t)Sn * 3072, 64,
        qkvh + 1024, qkvl + 1024, 3072, (size_t)Sn * 3072, 64,
        nullptr, nullptr, sc, nullptr, nullptr, 1024, 16 * ZST, ZST, 64, 0, 1, 0);
    softmax_split<<<64 * Sn, 256>>>(sc, SCALE, 1, nullptr, ph, pl);
    tgemm<64><<<dim3(1, 8, 64), 256, SM64>>>(                          // ctx = P.V
        ph, pl, 1024, 16 * ZST, ZST,
        vth, vtl, 1024, (size_t)16 * 64 * 1024, (size_t)64 * 1024,
        nullptr, nullptr, nullptr, ctxh, ctxl, 1024, (size_t)Sn * Dn, 64, 1024, 0, 0, 1);
    tgemm<256><<<dim3(4, M / 128, 1), 256, SM256>>>(
        ctxh, ctxl, 1024, 0, 0, wth + OW_AO, wtl + OW_AO, 1024, 0, 0,
        ao_b, hid, hb, nullptr, nullptr, 1024, 0, 0, 1024, 0, 0, 0);

    // ==== cross-attention block ====
    ln_split<<<M, 256>>>(hb, ln2_w, ln2_b, lnh, lnl);
    tgemm<256><<<dim3(4, M / 128, 1), 256, SM256>>>(
        lnh, lnl, 1024, 0, 0, wth + OW_Q, wtl + OW_Q, 1024, 0, 0,
        q_b, nullptr, nullptr, qh, ql, 1024, 0, 0, 1024, 0, 0, 0);
    tgemm<256><<<dim3(8, M / 128, 1), 256, SM256>>>(
        ench, encl, 1024, 0, 0, wth + OW_KV, wtl + OW_KV, 1024, 0, 0,
        kv_b, nullptr, nullptr, kvh, kvl, 2048, 0, 0, 1024, 0, 0, 0);
    vtransT<<<dim3(32, 2, 64), 256>>>(kvh, kvl, 2048, 1024, vth, vtl);
    tgemm<128><<<dim3(8, 8, 64), 256, SM128>>>(
        qh, ql, 1024, (size_t)Sn * 1024, 64,
        kvh, kvl, 2048, (size_t)Sn * 2048, 64,
        nullptr, nullptr, sc, nullptr, nullptr, 1024, 16 * ZST, ZST, 64, 0, 0, 0);
    softmax_split<<<64 * Sn, 256>>>(sc, SCALE, 0, enc_mask, ph, pl);
    tgemm<64><<<dim3(1, 8, 64), 256, SM64>>>(
        ph, pl, 1024, 16 * ZST, ZST,
        vth, vtl, 1024, (size_t)16 * 64 * 1024, (size_t)64 * 1024,
        nullptr, nullptr, nullptr, ctxh, ctxl, 1024, (size_t)Sn * Dn, 64, 1024, 0, 0, 0);
    tgemm<256><<<dim3(4, M / 128, 1), 256, SM256>>>(
        ctxh, ctxl, 1024, 0, 0, wth + OW_CO, wtl + OW_CO, 1024, 0, 0,
        co_b, hb, hb, nullptr, nullptr, 1024, 0, 0, 1024, 0, 0, 0);

    // ==== FFN block ====
    ln_split<<<M, 256>>>(hb, ln3_w, ln3_b, lnh, lnl);
    tgemm<256><<<dim3(16, M / 128, 1), 256, SM256>>>(
        lnh, lnl, 1024, 0, 0, wth + OW_FI, wtl + OW_FI, 1024, 0, 0,
        fi_b, nullptr, nullptr, ffnh, ffnl, 4096, 0, 0, 1024, 1, 0, 0);
    tgemm<256><<<dim3(4, M / 128, 1), 256, SM256>>>(
        ffnh, ffnl, 4096, 0, 0, wth + OW_FO, wtl + OW_FO, 4096, 0, 0,
        fo_b, hb, out, nullptr, nullptr, 1024, 0, 0, 4096, 0, 0, 0);
}

// round 9
// speedup vs baseline: 2.6829x; 1.1108x over previous
#include <cuda_runtime.h>
#include <cuda_bf16.h>
#include <math.h>
#include <stdint.h>

// Problem constants
constexpr int Bn = 4, Sn = 1024, Tn = 1024, Dn = 1024, Fn = 4096;
constexpr int Mrows = Bn * Sn;           // 4096
constexpr float SCALE = 0.125f;          // 1/sqrt(64)

// ---------------- scratch (static device globals: allocation-free) -------------
__device__ __align__(256) float g_sc [(size_t)64 * Sn * Tn];   // 256 MB scores
__device__ __align__(256) float g_h  [Mrows * Dn];             // fp32 hidden

__device__ __align__(256) __nv_bfloat16 g_qkvh[Mrows * 3 * Dn];
__device__ __align__(256) __nv_bfloat16 g_qkvl[Mrows * 3 * Dn];
__device__ __align__(256) __nv_bfloat16 g_qh  [Mrows * Dn];
__device__ __align__(256) __nv_bfloat16 g_ql  [Mrows * Dn];
__device__ __align__(256) __nv_bfloat16 g_kvh [Mrows * 2 * Dn];
__device__ __align__(256) __nv_bfloat16 g_kvl [Mrows * 2 * Dn];
__device__ __align__(256) __nv_bfloat16 g_ph  [(size_t)64 * Sn * Tn];
__device__ __align__(256) __nv_bfloat16 g_pl  [(size_t)64 * Sn * Tn];
__device__ __align__(256) __nv_bfloat16 g_vth [64 * 64 * 1024];
__device__ __align__(256) __nv_bfloat16 g_vtl [64 * 64 * 1024];

__device__ __align__(256) __nv_bfloat16 g_lnh [Mrows * Dn];
__device__ __align__(256) __nv_bfloat16 g_lnl [Mrows * Dn];
__device__ __align__(256) __nv_bfloat16 g_ctxh[Mrows * Dn];
__device__ __align__(256) __nv_bfloat16 g_ctxl[Mrows * Dn];
__device__ __align__(256) __nv_bfloat16 g_ench[Mrows * Dn];
__device__ __align__(256) __nv_bfloat16 g_encl[Mrows * Dn];
__device__ __align__(256) __nv_bfloat16 g_ffnh[(size_t)Mrows * Fn];
__device__ __align__(256) __nv_bfloat16 g_ffnl[(size_t)Mrows * Fn];
__device__ __align__(256) __nv_bfloat16 g_wth[16 * 1024 * 1024];
__device__ __align__(256) __nv_bfloat16 g_wtl[16 * 1024 * 1024];
constexpr size_t OW_QKV = 0;
constexpr size_t OW_AO  = OW_QKV + 3u*1024*1024;
constexpr size_t OW_Q   = OW_AO  + 1u*1024*1024;
constexpr size_t OW_KV  = OW_Q   + 1u*1024*1024;
constexpr size_t OW_CO  = OW_KV  + 2u*1024*1024;
constexpr size_t OW_FI  = OW_CO  + 1u*1024*1024;
constexpr size_t OW_FO  = OW_FI  + 4u*1024*1024;

// ================= helpers ======================================================
__device__ __forceinline__ uint32_t s2u(const void* p) {
    uint32_t a;
    asm("{ .reg .u64 t; cvta.to.shared.u64 t, %1; cvt.u32.u64 %0, t; }" : "=r"(a) : "l"(p));
    return a;
}
__device__ __forceinline__ void ldsm4(uint32_t& r0, uint32_t& r1, uint32_t& r2, uint32_t& r3,
                                      uint32_t a) {
    asm volatile("ldmatrix.sync.aligned.m8n8.x4.shared.b16 {%0,%1,%2,%3}, [%4];"
        : "=r"(r0), "=r"(r1), "=r"(r2), "=r"(r3) : "r"(a));
}
__device__ __forceinline__ void mma16816(float* c, const uint32_t* a, uint32_t b0, uint32_t b1) {
    asm volatile(
        "mma.sync.aligned.m16n8k16.row.col.f32.bf16.bf16.f32 "
        "{%0,%1,%2,%3}, {%4,%5,%6,%7}, {%8,%9}, {%0,%1,%2,%3};"
        : "+f"(c[0]), "+f"(c[1]), "+f"(c[2]), "+f"(c[3])
        : "r"(a[0]), "r"(a[1]), "r"(a[2]), "r"(a[3]), "r"(b0), "r"(b1));
}
__device__ __forceinline__ void cpa16(uint32_t dst, const void* src) {
    asm volatile("cp.async.ca.shared.global [%0], [%1], 16;" :: "r"(dst), "l"(src));
}
__device__ __forceinline__ void split2(float x, __nv_bfloat16& h, __nv_bfloat16& l) {
    h = __float2bfloat16(x);
    l = __float2bfloat16(x - __bfloat162float(h));
}

// ================= tensor-core split-bf16 GEMM (mma.sync HMMA) ==================
// Batched: z = blockIdx.z, b=z>>4, h=z&15; operand offset = b*sXb + h*sXh.
// A split [*,K] (row stride lda), B split [N,K] (row stride ldb), both K-major.
// C = A@B^T (+bias)(+GELU)(+res); outputs fp32 (Cf) and/or split bf16 (Ch/Cl).
// trimask: skip tiles fully above the causal diagonal. kcausal: clamp K to the
// 128-row block's causal frontier. __launch_bounds__(256,2): cap regs at 128 so
// two CTAs co-reside per SM — one CTA's MMA work hides the other's cp.async
// wait + barrier latency.
template<int BN>
__global__ __launch_bounds__(256, 2)
void tgemm(const __nv_bfloat16* __restrict__ Ah_, const __nv_bfloat16* __restrict__ Al_,
           int lda, size_t sAb, size_t sAh,
           const __nv_bfloat16* __restrict__ Bh_, const __nv_bfloat16* __restrict__ Bl_,
           int ldb, size_t sBb, size_t sBh,
           const float* __restrict__ bias, const float* __restrict__ res,
           float* __restrict__ Cf, __nv_bfloat16* __restrict__ Ch, __nv_bfloat16* __restrict__ Cl,
           int ldc, size_t sCb, size_t sCh,
           int K, int gelu, int trimask, int kcausal)
{
    constexpr int STAGE = 16384 + BN * 128;      // bytes per pipeline stage
    constexpr int LP    = (128 + BN) * 8 / 256;  // 16B loads per thread per stage
    constexpr int NTC   = BN / 16;               // 8-col n-tiles per warp
    constexpr int NJ    = BN / 32;               // ldsm-b iterations

    extern __shared__ __align__(1024) char smraw[];
    const uint32_t sbase = s2u(smraw);
    const int tid = threadIdx.x, lane = tid & 31, wid = tid >> 5;
    const int z = blockIdx.z, zb = z >> 4, zh = z & 15;
    const int m0 = blockIdx.y * 128, n0 = blockIdx.x * BN;
    const int wm = wid & 3, wn = wid >> 2;

    if (trimask && n0 > m0 + 127) return;        // fully-masked causal tile
    const int Ke = kcausal ? min(K, ((m0 >> 8) + 1) << 8) : K;

    const __nv_bfloat16* Ahp = Ah_ + zb * sAb + zh * sAh + (size_t)m0 * lda;
    const __nv_bfloat16* Alp = Al_ + zb * sAb + zh * sAh + (size_t)m0 * lda;
    const __nv_bfloat16* Bhp = Bh_ + zb * sBb + zh * sBh + (size_t)n0 * ldb;
    const __nv_bfloat16* Blp = Bl_ + zb * sBb + zh * sBh + (size_t)n0 * ldb;
    const size_t coff = zb * sCb + zh * sCh;

    float acc[2][NTC][4] = {};

    auto stage = [&](int st, int k0) {
        uint32_t dst0 = sbase + st * STAGE;
        #pragma unroll
        for (int p = 0; p < LP; p++) {
            int idx = tid + p * 256;
            int isB = idx >= 1024;
            int s = isB ? idx - 1024 : idx;
            int r = s >> 3, q = s & 7;
            const __nv_bfloat16* src = isB
                ? ((q < 4 ? Bhp : Blp) + (size_t)r * ldb + k0 + (q & 3) * 8)
                : ((q < 4 ? Ahp : Alp) + (size_t)r * lda + k0 + (q & 3) * 8);
            uint32_t dst = dst0 + isB * 16384 + r * 128 + ((q * 16) ^ ((r & 7) * 16));
            cpa16(dst, src);
        }
        asm volatile("cp.async.commit_group;" ::: "memory");
    };

    auto compute = [&](int st) {
        uint32_t sA = sbase + st * STAGE, sB = sA + 16384;
        #pragma unroll
        for (int ks = 0; ks < 2; ks++) {
            uint32_t ah[2][4], al[2][4];
            #pragma unroll
            for (int mt = 0; mt < 2; mt++) {
                int row = wm * 32 + mt * 16 + (lane & 15);
                int kb = ks * 32 + (lane >> 4) * 16;
                uint32_t rb = sA + row * 128;
                uint32_t xr = (row & 7) * 16;
                ldsm4(ah[mt][0], ah[mt][1], ah[mt][2], ah[mt][3], rb + (kb ^ xr));
                ldsm4(al[mt][0], al[mt][1], al[mt][2], al[mt][3], rb + ((kb + 64) ^ xr));
            }
            #pragma unroll
            for (int j = 0; j < NJ; j++) {
                int g = lane >> 3;
                int row = wn * (BN / 2) + (j * 2 + (g >> 1)) * 8 + (lane & 7);
                int kb = ks * 32 + (g & 1) * 16;
                uint32_t rb = sB + row * 128;
                uint32_t xr = (row & 7) * 16;
                uint32_t bh[4], bl[4];
                ldsm4(bh[0], bh[1], bh[2], bh[3], rb + (kb ^ xr));
                ldsm4(bl[0], bl[1], bl[2], bl[3], rb + ((kb + 64) ^ xr));
                #pragma unroll
                for (int mt = 0; mt < 2; mt++) {
                    #pragma unroll
                    for (int t = 0; t < 2; t++) {
                        float* c = acc[mt][j * 2 + t];
                        mma16816(c, ah[mt], bh[2 * t], bh[2 * t + 1]);
                        mma16816(c, ah[mt], bl[2 * t], bl[2 * t + 1]);
                        mma16816(c, al[mt], bh[2 * t], bh[2 * t + 1]);
                    }
                }
            }
        }
    };

    const int NC = Ke >> 5;
    stage(0, 0);
    for (int c = 0; c < NC; c++) {
        asm volatile("cp.async.wait_group 0;" ::: "memory");
        __syncthreads();
        if (c + 1 < NC) stage((c + 1) & 1, (c + 1) * 32);
        compute(c & 1);
    }

    // ---- epilogue ----
    const int r_in = lane >> 2, c_in = (lane & 3) * 2;
    #pragma unroll
    for (int mt = 0; mt < 2; mt++) {
        #pragma unroll
        for (int rr = 0; rr < 2; rr++) {
            int row = m0 + wm * 32 + mt * 16 + rr * 8 + r_in;
            #pragma unroll
            for (int nt = 0; nt < NTC; nt++) {
                int col = n0 + wn * (BN / 2) + nt * 8 + c_in;
                float v0 = acc[mt][nt][rr * 2 + 0];
                float v1 = acc[mt][nt][rr * 2 + 1];
                if (bias) { v0 += bias[col]; v1 += bias[col + 1]; }
                if (gelu) {
                    v0 = 0.5f * v0 * (1.0f + erff(v0 * 0.7071067811865476f));
                    v1 = 0.5f * v1 * (1.0f + erff(v1 * 0.7071067811865476f));
                }
                size_t off = coff + (size_t)row * ldc + col;
                if (res) {
                    float2 rr2 = *(const float2*)(res + off);
                    v0 += rr2.x; v1 += rr2.y;
                }
                if (Cf) *(float2*)(Cf + off) = make_float2(v0, v1);
                if (Ch) {
                    __nv_bfloat16 h0, l0, h1, l1;
                    split2(v0, h0, l0); split2(v1, h1, l1);
                    *(__nv_bfloat162*)(Ch + off) = __nv_bfloat162(h0, h1);
                    *(__nv_bfloat162*)(Cl + off) = __nv_bfloat162(l0, l1);
                }
            }
        }
    }
}

// ============== V transpose: vt[z][d][t] = v[(b*S+t)*ld + off + h*64 + d] =======
__global__ __launch_bounds__(256) void vtransT(
    const __nv_bfloat16* __restrict__ inh, const __nv_bfloat16* __restrict__ inl,
    int ld, int off, __nv_bfloat16* __restrict__ oth, __nv_bfloat16* __restrict__ otl)
{
    __shared__ __nv_bfloat16 th[32][33], tl[32][33];
    const int z = blockIdx.z, b = z >> 4, h = z & 15;
    const int t0 = blockIdx.x * 32, d0 = blockIdx.y * 32;
    const int tx = threadIdx.x & 31, ty = threadIdx.x >> 5;
    const __nv_bfloat16* sh = inh + (size_t)b * Sn * ld + off + h * 64 + d0;
    const __nv_bfloat16* sl = inl + (size_t)b * Sn * ld + off + h * 64 + d0;
    #pragma unroll
    for (int i = 0; i < 4; i++) {
        int t = t0 + ty + i * 8;
        th[ty + i * 8][tx] = sh[(size_t)t * ld + tx];
        tl[ty + i * 8][tx] = sl[(size_t)t * ld + tx];
    }
    __syncthreads();
    size_t obase = (size_t)z * 64 * 1024;
    #pragma unroll
    for (int i = 0; i < 4; i++) {
        int d = d0 + ty + i * 8;
        oth[obase + (size_t)d * 1024 + t0 + tx] = th[tx][ty + i * 8];
        otl[obase + (size_t)d * 1024 + t0 + tx] = tl[tx][ty + i * 8];
    }
}

// ============== weight transpose + split: W[K,N] -> Wh/Wl[N,K] bf16 =============
__global__ __launch_bounds__(256) void wsplitT(
    const float* __restrict__ W, __nv_bfloat16* __restrict__ oh,
    __nv_bfloat16* __restrict__ ol, int K, int N)
{
    __shared__ float t[32][33];
    int tx = threadIdx.x & 31, ty = threadIdx.x >> 5;
    int n0 = blockIdx.x * 32, k0 = blockIdx.y * 32;
    #pragma unroll
    for (int i = 0; i < 4; i++)
        t[ty + i * 8][tx] = W[(size_t)(k0 + ty + i * 8) * N + n0 + tx];
    __syncthreads();
    #pragma unroll
    for (int i = 0; i < 4; i++) {
        float v = t[tx][ty + i * 8];
        __nv_bfloat16 h, l;
        split2(v, h, l);
        size_t o = (size_t)(n0 + ty + i * 8) * K + k0 + tx;
        oh[o] = h; ol[o] = l;
    }
}

// ============== elementwise split (enc hidden states) ===========================
__global__ __launch_bounds__(256) void esplit(
    const float* __restrict__ x, __nv_bfloat16* __restrict__ oh,
    __nv_bfloat16* __restrict__ ol)
{
    int i = blockIdx.x * 256 + threadIdx.x;
    float4 v = ((const float4*)x)[i];
    __nv_bfloat16 h0, l0, h1, l1, h2, l2, h3, l3;
    split2(v.x, h0, l0); split2(v.y, h1, l1); split2(v.z, h2, l2); split2(v.w, h3, l3);
    ((__nv_bfloat162*)oh)[2 * i]     = __nv_bfloat162(h0, h1);
    ((__nv_bfloat162*)oh)[2 * i + 1] = __nv_bfloat162(h2, h3);
    ((__nv_bfloat162*)ol)[2 * i]     = __nv_bfloat162(l0, l1);
    ((__nv_bfloat162*)ol)[2 * i + 1] = __nv_bfloat162(l2, l3);
}

// ============== LayerNorm -> split bf16 =========================================
__global__ __launch_bounds__(256) void ln_split(
    const float* __restrict__ x, const float* __restrict__ w,
    const float* __restrict__ bb, __nv_bfloat16* __restrict__ yh,
    __nv_bfloat16* __restrict__ yl)
{
    const int row = blockIdx.x, tid = threadIdx.x;
    float4 v = ((const float4*)(x + (size_t)row * Dn))[tid];
    float s  = v.x + v.y + v.z + v.w;
    float sq = v.x * v.x + v.y * v.y + v.z * v.z + v.w * v.w;

    __shared__ float sm[18];
    #pragma unroll
    for (int off = 16; off > 0; off >>= 1) {
        s  += __shfl_xor_sync(~0u, s,  off);
        sq += __shfl_xor_sync(~0u, sq, off);
    }
    if ((tid & 31) == 0) { sm[tid >> 5] = s; sm[(tid >> 5) + 8] = sq; }
    __syncthreads();
    if (tid < 32) {
        float a  = (tid < 8) ? sm[tid]     : 0.f;
        float aq = (tid < 8) ? sm[tid + 8] : 0.f;
        #pragma unroll
        for (int off = 4; off > 0; off >>= 1) {
            a  += __shfl_xor_sync(~0u, a,  off);
            aq += __shfl_xor_sync(~0u, aq, off);
        }
        if (tid == 0) { sm[16] = a; sm[17] = aq; }
    }
    __syncthreads();
    const float mean = sm[16] * (1.0f / Dn);
    const float var  = sm[17] * (1.0f / Dn) - mean * mean;
    const float rstd = rsqrtf(var + 1e-12f);

    float4 w4 = ((const float4*)w)[tid];
    float4 b4 = ((const float4*)bb)[tid];
    float o0 = w4.x * (v.x - mean) * rstd + b4.x;
    float o1 = w4.y * (v.y - mean) * rstd + b4.y;
    float o2 = w4.z * (v.z - mean) * rstd + b4.z;
    float o3 = w4.w * (v.w - mean) * rstd + b4.w;
    __nv_bfloat16 h0, l0, h1, l1, h2, l2, h3, l3;
    split2(o0, h0, l0); split2(o1, h1, l1); split2(o2, h2, l2); split2(o3, h3, l3);
    size_t base = (size_t)row * Dn + tid * 4;
    ((__nv_bfloat162*)(yh + base))[0] = __nv_bfloat162(h0, h1);
    ((__nv_bfloat162*)(yh + base))[1] = __nv_bfloat162(h2, h3);
    ((__nv_bfloat162*)(yl + base))[0] = __nv_bfloat162(l0, l1);
    ((__nv_bfloat162*)(yl + base))[1] = __nv_bfloat162(l2, l3);
}

// ============== softmax: fp32 scores -> split-bf16 probs ========================
// causal: only process cols <= s (256-col chunks); masked cols get prob 0
// (matches reference: score -10000 -> exp underflows to exactly 0).
__global__ __launch_bounds__(256) void softmax_split(
    const float* __restrict__ sc, float scale, int causal,
    const float* __restrict__ addmask,
    __nv_bfloat16* __restrict__ ph, __nv_bfloat16* __restrict__ pl)
{
    const int row = blockIdx.x;
    const int s = row & (Sn - 1);
    const int b = row >> 14;
    const float* p = sc + (size_t)row * Tn;
    const int tid = threadIdx.x;

    const int ni = causal ? (s >> 8) + 1 : 4;   // 256-col chunks to process

    float vals[4];
    float mx = -1e30f;
    for (int i = 0; i < ni; i++) {
        int c = tid + i * 256;
        float v;
        if (causal && c > s) v = -10000.0f;
        else {
            v = p[c] * scale;
            if (!causal && addmask) v += addmask[(size_t)b * Tn + c];
        }
        vals[i] = v;
        mx = fmaxf(mx, v);
    }
    __shared__ float sm[18];
    #pragma unroll
    for (int off = 16; off > 0; off >>= 1) mx = fmaxf(mx, __shfl_xor_sync(~0u, mx, off));
    if ((tid & 31) == 0) sm[tid >> 5] = mx;
    __syncthreads();
    if (tid < 32) {
        float a = (tid < 8) ? sm[tid] : -1e30f;
        #pragma unroll
        for (int off = 4; off > 0; off >>= 1) a = fmaxf(a, __shfl_xor_sync(~0u, a, off));
        if (tid == 0) sm[16] = a;
    }
    __syncthreads();
    const float m = sm[16];

    float sum = 0.f;
    for (int i = 0; i < ni; i++) { vals[i] = expf(vals[i] - m); sum += vals[i]; }
    #pragma unroll
    for (int off = 16; off > 0; off >>= 1) sum += __shfl_xor_sync(~0u, sum, off);
    if ((tid & 31) == 0) sm[tid >> 5] = sum;
    __syncthreads();
    if (tid < 32) {
        float a = (tid < 8) ? sm[tid] : 0.f;
        #pragma unroll
        for (int off = 4; off > 0; off >>= 1) a += __shfl_xor_sync(~0u, a, off);
        if (tid == 0) sm[17] = a;
    }
    __syncthreads();
    const float inv = 1.0f / sm[17];
    for (int i = 0; i < ni; i++) {
        int c = tid + i * 256;
        __nv_bfloat16 hh, ll;
        split2(vals[i] * inv, hh, ll);
        ph[(size_t)row * Tn + c] = hh;
        pl[(size_t)row * Tn + c] = ll;
    }
}

// -------------------------------- launcher --------------------------------------
extern "C" void kernel_launch(void* const* d_in, const int* in_sizes, int n_in,
                              void* d_out, int out_size)
{
    const float* hid      = (const float*)d_in[0];
    const float* enc      = (const float*)d_in[1];
    const float* enc_mask = (const float*)d_in[2];
    const float *ln1_w = (const float*)d_in[4],  *ln1_b = (const float*)d_in[5];
    const float *qkv_w = (const float*)d_in[6],  *qkv_b = (const float*)d_in[7];
    const float *ao_w  = (const float*)d_in[8],  *ao_b  = (const float*)d_in[9];
    const float *ln2_w = (const float*)d_in[10], *ln2_b = (const float*)d_in[11];
    const float *q_w   = (const float*)d_in[12], *q_b   = (const float*)d_in[13];
    const float *kv_w  = (const float*)d_in[14], *kv_b  = (const float*)d_in[15];
    const float *co_w  = (const float*)d_in[16], *co_b  = (const float*)d_in[17];
    const float *ln3_w = (const float*)d_in[18], *ln3_b = (const float*)d_in[19];
    const float *fi_w  = (const float*)d_in[20], *fi_b  = (const float*)d_in[21];
    const float *fo_w  = (const float*)d_in[22], *fo_b  = (const float*)d_in[23];
    float* out = (float*)d_out;

    float *sc, *hb;
    __nv_bfloat16 *qkvh, *qkvl, *qh, *ql, *kvh, *kvl, *ph, *pl, *vth, *vtl;
    __nv_bfloat16 *lnh, *lnl, *ctxh, *ctxl, *ench, *encl, *ffnh, *ffnl, *wth, *wtl;
    cudaGetSymbolAddress((void**)&sc,   g_sc);
    cudaGetSymbolAddress((void**)&hb,   g_h);
    cudaGetSymbolAddress((void**)&qkvh, g_qkvh);
    cudaGetSymbolAddress((void**)&qkvl, g_qkvl);
    cudaGetSymbolAddress((void**)&qh,   g_qh);
    cudaGetSymbolAddress((void**)&ql,   g_ql);
    cudaGetSymbolAddress((void**)&kvh,  g_kvh);
    cudaGetSymbolAddress((void**)&kvl,  g_kvl);
    cudaGetSymbolAddress((void**)&ph,   g_ph);
    cudaGetSymbolAddress((void**)&pl,   g_pl);
    cudaGetSymbolAddress((void**)&vth,  g_vth);
    cudaGetSymbolAddress((void**)&vtl,  g_vtl);
    cudaGetSymbolAddress((void**)&lnh,  g_lnh);
    cudaGetSymbolAddress((void**)&lnl,  g_lnl);
    cudaGetSymbolAddress((void**)&ctxh, g_ctxh);
    cudaGetSymbolAddress((void**)&ctxl, g_ctxl);
    cudaGetSymbolAddress((void**)&ench, g_ench);
    cudaGetSymbolAddress((void**)&encl, g_encl);
    cudaGetSymbolAddress((void**)&ffnh, g_ffnh);
    cudaGetSymbolAddress((void**)&ffnl, g_ffnl);
    cudaGetSymbolAddress((void**)&wth,  g_wth);
    cudaGetSymbolAddress((void**)&wtl,  g_wtl);

    static bool attr_done = false;
    if (!attr_done) {
        cudaFuncSetAttribute(tgemm<128>, cudaFuncAttributeMaxDynamicSharedMemorySize, 65536);
        cudaFuncSetAttribute(tgemm<64>,  cudaFuncAttributeMaxDynamicSharedMemorySize, 49152);
        attr_done = true;
    }
    const int SM128 = 65536, SM64 = 49152;
    const int M = Mrows;  // 4096
    const size_t ZST = (size_t)Sn * Tn;

    // ---- weight conversion (transpose + split) ----
    wsplitT<<<dim3(3072 / 32, 1024 / 32), 256>>>(qkv_w, wth + OW_QKV, wtl + OW_QKV, 1024, 3072);
    wsplitT<<<dim3(1024 / 32, 1024 / 32), 256>>>(ao_w,  wth + OW_AO,  wtl + OW_AO,  1024, 1024);
    wsplitT<<<dim3(1024 / 32, 1024 / 32), 256>>>(q_w,   wth + OW_Q,   wtl + OW_Q,   1024, 1024);
    wsplitT<<<dim3(2048 / 32, 1024 / 32), 256>>>(kv_w,  wth + OW_KV,  wtl + OW_KV,  1024, 2048);
    wsplitT<<<dim3(1024 / 32, 1024 / 32), 256>>>(co_w,  wth + OW_CO,  wtl + OW_CO,  1024, 1024);
    wsplitT<<<dim3(4096 / 32, 1024 / 32), 256>>>(fi_w,  wth + OW_FI,  wtl + OW_FI,  1024, 4096);
    wsplitT<<<dim3(1024 / 32, 4096 / 32), 256>>>(fo_w,  wth + OW_FO,  wtl + OW_FO,  4096, 1024);
    esplit<<<(M * Dn / 4) / 256, 256>>>(enc, ench, encl);

    // ==== self-attention block ====
    ln_split<<<M, 256>>>(hid, ln1_w, ln1_b, lnh, lnl);
    tgemm<128><<<dim3(24, M / 128, 1), 256, SM128>>>(
        lnh, lnl, 1024, 0, 0, wth + OW_QKV, wtl + OW_QKV, 1024, 0, 0,
        qkv_b, nullptr, nullptr, qkvh, qkvl, 3072, 0, 0, 1024, 0, 0, 0);
    vtransT<<<dim3(32, 2, 64), 256>>>(qkvh, qkvl, 3072, 2048, vth, vtl);
    tgemm<128><<<dim3(8, 8, 64), 256, SM128>>>(                       // scores = Q.K^T
        qkvh, qkvl, 3072, (size_t)Sn * 3072, 64,
        qkvh + 1024, qkvl + 1024, 3072, (size_t)Sn * 3072, 64,
        nullptr, nullptr, sc, nullptr, nullptr, 1024, 16 * ZST, ZST, 64, 0, 1, 0);
    softmax_split<<<64 * Sn, 256>>>(sc, SCALE, 1, nullptr, ph, pl);
    tgemm<64><<<dim3(1, 8, 64), 256, SM64>>>(                          // ctx = P.V
        ph, pl, 1024, 16 * ZST, ZST,
        vth, vtl, 1024, (size_t)16 * 64 * 1024, (size_t)64 * 1024,
        nullptr, nullptr, nullptr, ctxh, ctxl, 1024, (size_t)Sn * Dn, 64, 1024, 0, 0, 1);
    tgemm<128><<<dim3(8, M / 128, 1), 256, SM128>>>(
        ctxh, ctxl, 1024, 0, 0, wth + OW_AO, wtl + OW_AO, 1024, 0, 0,
        ao_b, hid, hb, nullptr, nullptr, 1024, 0, 0, 1024, 0, 0, 0);

    // ==== cross-attention block ====
    ln_split<<<M, 256>>>(hb, ln2_w, ln2_b, lnh, lnl);
    tgemm<128><<<dim3(8, M / 128, 1), 256, SM128>>>(
        lnh, lnl, 1024, 0, 0, wth + OW_Q, wtl + OW_Q, 1024, 0, 0,
        q_b, nullptr, nullptr, qh, ql, 1024, 0, 0, 1024, 0, 0, 0);
    tgemm<128><<<dim3(16, M / 128, 1), 256, SM128>>>(
        ench, encl, 1024, 0, 0, wth + OW_KV, wtl + OW_KV, 1024, 0, 0,
        kv_b, nullptr, nullptr, kvh, kvl, 2048, 0, 0, 1024, 0, 0, 0);
    vtransT<<<dim3(32, 2, 64), 256>>>(kvh, kvl, 2048, 1024, vth, vtl);
    tgemm<128><<<dim3(8, 8, 64), 256, SM128>>>(
        qh, ql, 1024, (size_t)Sn * 1024, 64,
        kvh, kvl, 2048, (size_t)Sn * 2048, 64,
        nullptr, nullptr, sc, nullptr, nullptr, 1024, 16 * ZST, ZST, 64, 0, 0, 0);
    softmax_split<<<64 * Sn, 256>>>(sc, SCALE, 0, enc_mask, ph, pl);
    tgemm<64><<<dim3(1, 8, 64), 256, SM64>>>(
        ph, pl, 1024, 16 * ZST, ZST,
        vth, vtl, 1024, (size_t)16 * 64 * 1024, (size_t)64 * 1024,
        nullptr, nullptr, nullptr, ctxh, ctxl, 1024, (size_t)Sn * Dn, 64, 1024, 0, 0, 0);
    tgemm<128><<<dim3(8, M / 128, 1), 256, SM128>>>(
        ctxh, ctxl, 1024, 0, 0, wth + OW_CO, wtl + OW_CO, 1024, 0, 0,
        co_b, hb, hb, nullptr, nullptr, 1024, 0, 0, 1024, 0, 0, 0);

    // ==== FFN block ====
    ln_split<<<M, 256>>>(hb, ln3_w, ln3_b, lnh, lnl);
    tgemm<128><<<dim3(32, M / 128, 1), 256, SM128>>>(
        lnh, lnl, 1024, 0, 0, wth + OW_FI, wtl + OW_FI, 1024, 0, 0,
        fi_b, nullptr, nullptr, ffnh, ffnl, 4096, 0, 0, 1024, 1, 0, 0);
    tgemm<128><<<dim3(8, M / 128, 1), 256, SM128>>>(
        ffnh, ffnl, 4096, 0, 0, wth + OW_FO, wtl + OW_FO, 4096, 0, 0,
        fo_b, hb, out, nullptr, nullptr, 1024, 0, 0, 4096, 0, 0, 0);
}